// round 15
// baseline (speedup 1.0000x reference)
#include <cuda_runtime.h>
#include <cuda_fp16.h>
#include <math.h>
#include <stdint.h>

#define Bb   8
#define Nn   64
#define Hh   1024
#define BN   512
#define MAXP 32768
#define NEGV -1e30f

// ------------------------------- scratch ------------------------------------
__device__ __half g_Ehp[2][2][(size_t)MAXP * Hh];   // [graph][{E1pre, E2pre}] fp16
__device__ float  g_emb32[2][(size_t)BN * Hh];
__device__ __half g_embh[4][(size_t)BN * Hh];       // [pp*2+g]
__device__ __half g_embl[2][(size_t)BN * Hh];       // lo split of current emb
__device__ float  g_ndx[2][(size_t)BN * Hh];
__device__ float  g_ndsx[2][(size_t)BN * Hh];
__device__ float  g_t[(size_t)BN * Hh];
__device__ __half g_uh[2][(size_t)BN * Hh];
__device__ __half g_fnh[2][(size_t)BN * Hh];
__device__ __half g_wth[9][(size_t)Hh * Hh];
__device__ __half g_afh[2][(size_t)Hh * Hh];        // aff^T hi
__device__ __half g_afl[2][(size_t)Hh * Hh];        // aff^T lo
__device__ float  g_alpha[(size_t)1025 * Hh];
__device__ float  g_beta[(size_t)1025 * Hh];
__device__ float  g_bt[1024];
__device__ int    g_bc[1024];
__device__ float  g_b0a[16 * 1024], g_b0b[16 * 1024];
__device__ float  g_da[16 * 1024],  g_db[16 * 1024];
__device__ float  g_offa[16 * 1024], g_offb[16 * 1024];
__device__ float  g_ssk[Bb * Nn * Nn];
__device__ int    g_rowcnt[2][BN];
__device__ int    g_rowptr[2][BN + 1];
__device__ int    g_colj[2][MAXP];
__device__ int    g_esrc[2][MAXP];
__device__ float  g_aval[2][MAXP];
__device__ int    g_cnt[2];

// ---- streams/events created at static-init ----------------------------------
struct GInit {
    cudaStream_t s2;
    cudaEvent_t evRoot, evA, evW, evB, evD, evE;
    GInit() {
        cudaStreamCreateWithFlags(&s2, cudaStreamNonBlocking);
        cudaEventCreateWithFlags(&evRoot, cudaEventDisableTiming);
        cudaEventCreateWithFlags(&evA, cudaEventDisableTiming);
        cudaEventCreateWithFlags(&evW, cudaEventDisableTiming);
        cudaEventCreateWithFlags(&evB, cudaEventDisableTiming);
        cudaEventCreateWithFlags(&evD, cudaEventDisableTiming);
        cudaEventCreateWithFlags(&evE, cudaEventDisableTiming);
    }
};
static GInit g_si;

// ------------------------------- helpers ------------------------------------
__device__ __forceinline__ uint32_t smem_u32(const void* p) {
    uint32_t a;
    asm("{ .reg .u64 t; cvta.to.shared.u64 t, %1; cvt.u32.u64 %0, t; }" : "=r"(a) : "l"(p));
    return a;
}
#define MMA16816(d, a, b) \
    asm volatile("mma.sync.aligned.m16n8k16.row.col.f32.f16.f16.f32 " \
        "{%0,%1,%2,%3}, {%4,%5,%6,%7}, {%8,%9}, {%0,%1,%2,%3};" \
        : "+f"((d)[0]), "+f"((d)[1]), "+f"((d)[2]), "+f"((d)[3]) \
        : "r"((a)[0]), "r"((a)[1]), "r"((a)[2]), "r"((a)[3]), \
          "r"((b)[0]), "r"((b)[1]))
#define MMA16816H(d, a, b) \
    asm volatile("mma.sync.aligned.m16n8k16.row.col.f16.f16.f16.f16 " \
        "{%0,%1}, {%2,%3,%4,%5}, {%6,%7}, {%0,%1};" \
        : "+r"((d)[0]), "+r"((d)[1]) \
        : "r"((a)[0]), "r"((a)[1]), "r"((a)[2]), "r"((a)[3]), \
          "r"((b)[0]), "r"((b)[1]))
#define LDSM4(r0, r1, r2, r3, addr) \
    asm volatile("ldmatrix.sync.aligned.m8n8.x4.shared.b16 {%0,%1,%2,%3}, [%4];" \
        : "=r"(r0), "=r"(r1), "=r"(r2), "=r"(r3) : "r"(addr))
#define CPA16(dst, src, nbytes) \
    asm volatile("cp.async.ca.shared.global [%0], [%1], 16, %2;" \
        :: "r"(dst), "l"(src), "r"(nbytes))
#define CPA_COMMIT() asm volatile("cp.async.commit_group;")
#define CPA_WAIT0()  asm volatile("cp.async.wait_group 0;")

// ---------------- fp32-accumulate GEMM (node/cross/affinity) -----------------
__global__ void __launch_bounds__(256, 2)
k_hgemm(const __half* __restrict__ A0, const __half* __restrict__ A1g,
        const __half* __restrict__ A2, const __half* __restrict__ A3,
        const __half* __restrict__ B0, const __half* __restrict__ B1,
        const __half* __restrict__ B2, const __half* __restrict__ B3,
        const float* __restrict__ bias0, const float* __restrict__ bias1,
        float* __restrict__ C0, float* __restrict__ C1z,
        __half* __restrict__ Oh0, __half* __restrict__ Oh1g,
        int relu_a, int relu_oh, int zmode,
        int M, const int* __restrict__ Mptr)
{
    int z = blockIdx.z;
    const __half* A = A0;
    const __half* Bsel = B0;
    const float* bias = bias0;
    float* C = C0;
    __half* Oh = Oh0;
    if (zmode == 0) {
        if (Mptr) M = *Mptr;
        if (z == 1) { Bsel = B1; bias = bias1; C = C1z; Oh = nullptr; }
    } else {
        M = Mptr[z];
        if (z == 1) { A = A1g; Oh = Oh1g; C = C1z; }
    }
    int m0 = blockIdx.x << 7;
    if (m0 >= M) return;
    int n0 = blockIdx.y << 7;

    __shared__ __align__(16) char smraw[40960];
    uint32_t sb = smem_u32(smraw);
    const uint32_t STG = 2 * 128 * 40 * 2;
    const uint32_t OPS = 128 * 40 * 2;

    int t = threadIdx.x, lane = t & 31, wid = t >> 5;
    int wm = wid & 3, wn = wid >> 2;

    int lrow = t >> 1;
    int lhalf = (t & 1) << 4;
    size_t aoff = (size_t)(m0 + lrow) * Hh + lhalf;
    size_t boff = (size_t)(n0 + lrow) * Hh + lhalf;
    int abytes = (m0 + lrow < M) ? 16 : 0;
    uint32_t ldst = (uint32_t)(lrow * 40 + lhalf) * 2;

    float acc[2][8][4];
#pragma unroll
    for (int i = 0; i < 2; i++)
#pragma unroll
        for (int j = 0; j < 8; j++)
#pragma unroll
            for (int k = 0; k < 4; k++) acc[i][j][k] = 0.f;

    const __half* PA[3] = { A, A2, A3 };
    const __half* PB[3] = { Bsel, B2, B3 };
    int npairs = A3 ? 3 : (A2 ? 2 : 1);
    int T = npairs << 5;

    auto prefetch = [&](int it, int stg) {
        int pr = it >> 5;
        const __half* pA = PA[pr] + aoff + ((it & 31) << 5);
        const __half* pB = PB[pr] + boff + ((it & 31) << 5);
        uint32_t dA = sb + (uint32_t)stg * STG + ldst;
        CPA16(dA, pA, abytes);
        CPA16(dA + 16, pA + 8, abytes);
        uint32_t dB = dA + OPS;
        CPA16(dB, pB, 16);
        CPA16(dB + 16, pB + 8, 16);
        CPA_COMMIT();
    };

    prefetch(0, 0);
    int fr = lane & 15;
    int fk = (lane >> 4) << 3;
    const __half2 z2 = __float2half2_rn(0.f);

    for (int it = 0; it < T; it++) {
        CPA_WAIT0();
        __syncthreads();
        if (it + 1 < T) prefetch(it + 1, (it + 1) & 1);
        uint32_t stage = sb + (uint32_t)(it & 1) * STG;
#pragma unroll
        for (int ks = 0; ks < 2; ks++) {
            int kc = ks << 4;
            uint32_t af[2][4];
#pragma unroll
            for (int mt = 0; mt < 2; mt++) {
                uint32_t addr = stage + (uint32_t)((wm * 32 + mt * 16 + fr) * 40 + kc + fk) * 2;
                LDSM4(af[mt][0], af[mt][1], af[mt][2], af[mt][3], addr);
                if (relu_a) {
#pragma unroll
                    for (int q = 0; q < 4; q++) {
                        __half2 h = *(__half2*)&af[mt][q];
                        h = __hmax2(h, z2);
                        af[mt][q] = *(uint32_t*)&h;
                    }
                }
            }
            uint32_t bf[8][2];
#pragma unroll
            for (int nq = 0; nq < 4; nq++) {
                uint32_t r0, r1, r2, r3;
                uint32_t addr = stage + OPS +
                    (uint32_t)((wn * 64 + nq * 16 + fr) * 40 + kc + fk) * 2;
                LDSM4(r0, r1, r2, r3, addr);
                bf[nq * 2][0] = r0; bf[nq * 2][1] = r2;
                bf[nq * 2 + 1][0] = r1; bf[nq * 2 + 1][1] = r3;
            }
#pragma unroll
            for (int mt = 0; mt < 2; mt++)
#pragma unroll
                for (int nt = 0; nt < 8; nt++)
                    MMA16816(acc[mt][nt], af[mt], bf[nt]);
        }
    }

    float* ssm = (float*)smraw;
#pragma unroll
    for (int half = 0; half < 2; half++) {
        __syncthreads();
        if (wn == half) {
#pragma unroll
            for (int mt = 0; mt < 2; mt++)
#pragma unroll
                for (int nt = 0; nt < 8; nt++) {
                    int r = wm * 32 + mt * 16 + (lane >> 2);
                    int cl = nt * 8 + ((lane & 3) << 1);
                    ssm[r * 68 + cl]           = acc[mt][nt][0];
                    ssm[r * 68 + cl + 1]       = acc[mt][nt][1];
                    ssm[(r + 8) * 68 + cl]     = acc[mt][nt][2];
                    ssm[(r + 8) * 68 + cl + 1] = acc[mt][nt][3];
                }
        }
        __syncthreads();
        int r = t >> 1, cl = (t & 1) << 5;
        if (m0 + r < M) {
            int gc = n0 + half * 64 + cl;
            size_t gb = (size_t)(m0 + r) * Hh + gc;
#pragma unroll
            for (int i = 0; i < 8; i++) {
                float4 v = *(float4*)&ssm[r * 68 + cl + i * 4];
                if (bias) {
                    float4 bv = *(const float4*)(bias + gc + i * 4);
                    v.x += bv.x; v.y += bv.y; v.z += bv.z; v.w += bv.w;
                }
                if (C) *(float4*)&C[gb + i * 4] = v;
                if (Oh) {
                    float v0 = v.x, v1 = v.y, v2 = v.z, v3 = v.w;
                    if (relu_oh) {
                        v0 = fmaxf(v0, 0.f); v1 = fmaxf(v1, 0.f);
                        v2 = fmaxf(v2, 0.f); v3 = fmaxf(v3, 0.f);
                    }
                    __half2 h01 = __floats2half2_rn(v0, v1);
                    __half2 h23 = __floats2half2_rn(v2, v3);
                    *(uint2*)&Oh[gb + i * 4] =
                        make_uint2(*(uint32_t*)&h01, *(uint32_t*)&h23);
                }
            }
        }
    }
}

// ---------------- fp16-accumulate GEMM (edge E2 ONLY — proven safe + faster) -
__global__ void __launch_bounds__(256, 2)
k_h16(const __half* __restrict__ A0, const __half* __restrict__ A1g,
      const __half* __restrict__ B0, const float* __restrict__ bias,
      __half* __restrict__ Oh0, __half* __restrict__ Oh1g,
      const int* __restrict__ Mptr)
{
    int z = blockIdx.z;
    const __half* A = z ? A1g : A0;
    __half* Oh = z ? Oh1g : Oh0;
    int M = Mptr[z];
    int m0 = blockIdx.x << 7;
    if (m0 >= M) return;
    int n0 = blockIdx.y << 7;

    __shared__ __align__(16) char smraw[40960];
    uint32_t sb = smem_u32(smraw);
    const uint32_t STG = 2 * 128 * 40 * 2;
    const uint32_t OPS = 128 * 40 * 2;

    int t = threadIdx.x, lane = t & 31, wid = t >> 5;
    int wm = wid & 3, wn = wid >> 2;

    int lrow = t >> 1;
    int lhalf = (t & 1) << 4;
    size_t aoff = (size_t)(m0 + lrow) * Hh + lhalf;
    size_t boff = (size_t)(n0 + lrow) * Hh + lhalf;
    int abytes = (m0 + lrow < M) ? 16 : 0;
    uint32_t ldst = (uint32_t)(lrow * 40 + lhalf) * 2;

    uint32_t acc[2][8][2];
#pragma unroll
    for (int i = 0; i < 2; i++)
#pragma unroll
        for (int j = 0; j < 8; j++) { acc[i][j][0] = 0u; acc[i][j][1] = 0u; }

    auto prefetch = [&](int it, int stg) {
        int ko = it << 5;
        const __half* pA = A + aoff + ko;
        const __half* pB = B0 + boff + ko;
        uint32_t dA = sb + (uint32_t)stg * STG + ldst;
        CPA16(dA, pA, abytes);
        CPA16(dA + 16, pA + 8, abytes);
        uint32_t dB = dA + OPS;
        CPA16(dB, pB, 16);
        CPA16(dB + 16, pB + 8, 16);
        CPA_COMMIT();
    };

    prefetch(0, 0);
    int fr = lane & 15;
    int fk = (lane >> 4) << 3;
    const __half2 z2 = __float2half2_rn(0.f);

    for (int it = 0; it < 32; it++) {
        CPA_WAIT0();
        __syncthreads();
        if (it + 1 < 32) prefetch(it + 1, (it + 1) & 1);
        uint32_t stage = sb + (uint32_t)(it & 1) * STG;
#pragma unroll
        for (int ks = 0; ks < 2; ks++) {
            int kc = ks << 4;
            uint32_t af[2][4];
#pragma unroll
            for (int mt = 0; mt < 2; mt++) {
                uint32_t addr = stage + (uint32_t)((wm * 32 + mt * 16 + fr) * 40 + kc + fk) * 2;
                LDSM4(af[mt][0], af[mt][1], af[mt][2], af[mt][3], addr);
#pragma unroll
                for (int q = 0; q < 4; q++) {
                    __half2 h = *(__half2*)&af[mt][q];
                    h = __hmax2(h, z2);
                    af[mt][q] = *(uint32_t*)&h;
                }
            }
            uint32_t bf[8][2];
#pragma unroll
            for (int nq = 0; nq < 4; nq++) {
                uint32_t r0, r1, r2, r3;
                uint32_t addr = stage + OPS +
                    (uint32_t)((wn * 64 + nq * 16 + fr) * 40 + kc + fk) * 2;
                LDSM4(r0, r1, r2, r3, addr);
                bf[nq * 2][0] = r0; bf[nq * 2][1] = r2;
                bf[nq * 2 + 1][0] = r1; bf[nq * 2 + 1][1] = r3;
            }
#pragma unroll
            for (int mt = 0; mt < 2; mt++)
#pragma unroll
                for (int nt = 0; nt < 8; nt++)
                    MMA16816H(acc[mt][nt], af[mt], bf[nt]);
        }
    }

    float* ssm = (float*)smraw;
#pragma unroll
    for (int half = 0; half < 2; half++) {
        __syncthreads();
        if (wn == half) {
#pragma unroll
            for (int mt = 0; mt < 2; mt++)
#pragma unroll
                for (int nt = 0; nt < 8; nt++) {
                    int r = wm * 32 + mt * 16 + (lane >> 2);
                    int cl = nt * 8 + ((lane & 3) << 1);
                    __half2 p0 = *(__half2*)&acc[mt][nt][0];
                    __half2 p1 = *(__half2*)&acc[mt][nt][1];
                    ssm[r * 68 + cl]           = __low2float(p0);
                    ssm[r * 68 + cl + 1]       = __high2float(p0);
                    ssm[(r + 8) * 68 + cl]     = __low2float(p1);
                    ssm[(r + 8) * 68 + cl + 1] = __high2float(p1);
                }
        }
        __syncthreads();
        int r = t >> 1, cl = (t & 1) << 5;
        if (m0 + r < M) {
            int gc = n0 + half * 64 + cl;
            size_t gb = (size_t)(m0 + r) * Hh + gc;
#pragma unroll
            for (int i = 0; i < 8; i++) {
                float4 v = *(float4*)&ssm[r * 68 + cl + i * 4];
                float4 bv = *(const float4*)(bias + gc + i * 4);
                v.x += bv.x; v.y += bv.y; v.z += bv.z; v.w += bv.w;
                __half2 h01 = __floats2half2_rn(v.x, v.y);
                __half2 h23 = __floats2half2_rn(v.z, v.w);
                *(uint2*)&Oh[gb + i * 4] =
                    make_uint2(*(uint32_t*)&h01, *(uint32_t*)&h23);
            }
        }
    }
}

// ------------------------- compaction (merged graphs) -----------------------
__global__ void k_count(const float* __restrict__ A0, const float* __restrict__ A1,
                        int* __restrict__ rowcnt) {
    int g = blockIdx.y;
    const float* A = g ? A1 : A0;
    int r = blockIdx.x * 64 + threadIdx.x;
    const float* row = A + (size_t)r * Nn;
    int c = 0;
    for (int j = 0; j < Nn; j++) c += (row[j] != 0.0f);
    rowcnt[g * BN + r] = c;
}
__global__ void k_scan(const int* __restrict__ rowcnt, int* __restrict__ rowptr,
                       int* __restrict__ cnt) {
    __shared__ int sm[BN];
    int g = blockIdx.x, t = threadIdx.x;
    sm[t] = rowcnt[g * BN + t];
    __syncthreads();
    for (int off = 1; off < BN; off <<= 1) {
        int v = (t >= off) ? sm[t - off] : 0;
        __syncthreads();
        sm[t] += v;
        __syncthreads();
    }
    rowptr[g * (BN + 1) + t + 1] = sm[t];
    if (t == 0)      rowptr[g * (BN + 1)] = 0;
    if (t == BN - 1) cnt[g] = sm[BN - 1];
}
__global__ void k_fill(const float* __restrict__ A0, const float* __restrict__ A1,
                       const int* __restrict__ rowptr,
                       int* __restrict__ colj, int* __restrict__ esrc,
                       float* __restrict__ aval) {
    int g = blockIdx.y;
    const float* A = g ? A1 : A0;
    int r = blockIdx.x * 64 + threadIdx.x;
    const float* row = A + (size_t)r * Nn;
    int pos = rowptr[g * (BN + 1) + r];
    for (int j = 0; j < Nn; j++) {
        float a = row[j];
        if (a != 0.0f) {
            colj[g * MAXP + pos] = j;
            esrc[g * MAXP + pos] = r * Nn + j;
            aval[g * MAXP + pos] = a;
            pos++;
        }
    }
}

// ---------------- PWL: sort breakpoints (bitonic, 1 block) ------------------
__global__ void k_sort(const float* __restrict__ ew, const float* __restrict__ eb,
                       float* __restrict__ bt, int* __restrict__ bc) {
    __shared__ float sk[1024];
    __shared__ int   sc[1024];
    int t = threadIdx.x;
    float e = ew[t];
    sk[t] = (e != 0.f) ? (-eb[t] / e) : 3.4e38f;
    sc[t] = t;
    __syncthreads();
    for (int k = 2; k <= 1024; k <<= 1) {
        for (int j = k >> 1; j > 0; j >>= 1) {
            int ixj = t ^ j;
            if (ixj > t) {
                float a = sk[t], b = sk[ixj];
                int ca = sc[t], cb = sc[ixj];
                bool gt = (a > b) || (a == b && ca > cb);
                bool up = ((t & k) == 0);
                if (gt == up) { sk[t] = b; sk[ixj] = a; sc[t] = cb; sc[ixj] = ca; }
            }
            __syncthreads();
        }
    }
    bt[t] = sk[t];
    bc[t] = sc[t];
}

// ---------------- PWL: base partials + delta sums (merged, MLP=4) -----------
__global__ void k_bd(const float* __restrict__ ew, const float* __restrict__ eb,
                     const float* __restrict__ W1, const float* __restrict__ b1,
                     const int* __restrict__ bc,
                     float* __restrict__ b0a, float* __restrict__ b0b,
                     float* __restrict__ da, float* __restrict__ db) {
    int col = blockIdx.x * 128 + threadIdx.x;
    int ch = blockIdx.y;
    if (blockIdx.z == 0) {
        float a = 0.f, b = (ch == 0) ? b1[col] : 0.f;
        for (int qb = 0; qb < 64; qb += 4) {
            float e[4], ebv[4], w[4];
#pragma unroll
            for (int i = 0; i < 4; i++) {
                int c = ch * 64 + qb + i;
                e[i] = ew[c]; ebv[i] = eb[c];
                w[i] = __ldg(&W1[(size_t)c * Hh + col]);
            }
#pragma unroll
            for (int i = 0; i < 4; i++) {
                if (e[i] < 0.f) { a += e[i] * w[i]; b += ebv[i] * w[i]; }
                else if (e[i] == 0.f && ebv[i] > 0.f) b += ebv[i] * w[i];
            }
        }
        b0a[ch * 1024 + col] = a;
        b0b[ch * 1024 + col] = b;
    } else {
        float a = 0.f, b = 0.f;
        for (int qb = 0; qb < 64; qb += 4) {
            float e[4], ebv[4], w[4];
#pragma unroll
            for (int i = 0; i < 4; i++) {
                int c = bc[ch * 64 + qb + i];
                e[i] = ew[c]; ebv[i] = eb[c];
                w[i] = __ldg(&W1[(size_t)c * Hh + col]);
            }
#pragma unroll
            for (int i = 0; i < 4; i++) {
                float s = (e[i] > 0.f) ? 1.f : ((e[i] < 0.f) ? -1.f : 0.f);
                a += s * e[i] * w[i];
                b += s * ebv[i] * w[i];
            }
        }
        da[ch * 1024 + col] = a;
        db[ch * 1024 + col] = b;
    }
}

// ---------------- PWL: chunk offsets + segment-0 row -------------------------
__global__ void k_offs(const float* __restrict__ b0a, const float* __restrict__ b0b,
                       const float* __restrict__ da, const float* __restrict__ db,
                       float* __restrict__ offa, float* __restrict__ offb,
                       float* __restrict__ alpha, float* __restrict__ beta) {
    int col = blockIdx.x * 128 + threadIdx.x;
    float a = 0.f, b = 0.f;
#pragma unroll
    for (int cc = 0; cc < 16; cc++) { a += b0a[cc * 1024 + col]; b += b0b[cc * 1024 + col]; }
    alpha[col] = a;
    beta[col] = b;
#pragma unroll
    for (int jc = 0; jc < 16; jc++) {
        offa[jc * 1024 + col] = a;
        offb[jc * 1024 + col] = b;
        a += da[jc * 1024 + col];
        b += db[jc * 1024 + col];
    }
}

// ---------------- PWL: fill rows 1..1024 (prefetch 4) ------------------------
__global__ void k_fillscan(const float* __restrict__ ew, const float* __restrict__ eb,
                           const float* __restrict__ W1, const int* __restrict__ bc,
                           const float* __restrict__ offa, const float* __restrict__ offb,
                           float* __restrict__ alpha, float* __restrict__ beta) {
    int col = blockIdx.x * 128 + threadIdx.x;
    int jc = blockIdx.y;
    float a = offa[jc * 1024 + col];
    float b = offb[jc * 1024 + col];
    for (int qb = 0; qb < 64; qb += 4) {
        float e[4], ebv[4], w[4];
#pragma unroll
        for (int i = 0; i < 4; i++) {
            int c = bc[jc * 64 + qb + i];
            e[i] = ew[c]; ebv[i] = eb[c];
            w[i] = __ldg(&W1[(size_t)c * Hh + col]);
        }
#pragma unroll
        for (int i = 0; i < 4; i++) {
            int j = jc * 64 + qb + i;
            float s = (e[i] > 0.f) ? 1.f : ((e[i] < 0.f) ? -1.f : 0.f);
            a += s * e[i] * w[i];
            b += s * ebv[i] * w[i];
            alpha[(size_t)(j + 1) * Hh + col] = a;
            beta[(size_t)(j + 1) * Hh + col] = b;
        }
    }
}

// ---------------- PWL eval (merged graphs, vectorized) -----------------------
__global__ void k_pwl(const float* __restrict__ fe0, const float* __restrict__ fe1,
                      const int* __restrict__ esrc, const int* __restrict__ cnt,
                      const float* __restrict__ bt,
                      const float* __restrict__ alpha, const float* __restrict__ beta,
                      __half* __restrict__ Ehp) {
    int g = blockIdx.y;
    int p = blockIdx.x;
    if (p >= cnt[g]) return;
    const float* fe = g ? fe1 : fe0;
    float f = fe[esrc[g * MAXP + p]];
    int lo = 0, hi = 1024;
    while (lo < hi) {
        int m = (lo + hi) >> 1;
        if (__ldg(&bt[m]) <= f) lo = m + 1; else hi = m;
    }
    const float4* ra = (const float4*)(alpha + (size_t)lo * Hh);
    const float4* rb = (const float4*)(beta + (size_t)lo * Hh);
    __half* E1 = Ehp + (size_t)g * 2 * ((size_t)MAXP * Hh) + (size_t)p * Hh;
    int c4 = threadIdx.x * 2;
    float4 a0 = __ldg(&ra[c4]),     a1 = __ldg(&ra[c4 + 1]);
    float4 b0 = __ldg(&rb[c4]),     b1 = __ldg(&rb[c4 + 1]);
    __half2 h0 = __floats2half2_rn(fmaf(f, a0.x, b0.x), fmaf(f, a0.y, b0.y));
    __half2 h1 = __floats2half2_rn(fmaf(f, a0.z, b0.z), fmaf(f, a0.w, b0.w));
    __half2 h2 = __floats2half2_rn(fmaf(f, a1.x, b1.x), fmaf(f, a1.y, b1.y));
    __half2 h3 = __floats2half2_rn(fmaf(f, a1.z, b1.z), fmaf(f, a1.w, b1.w));
    uint4 o;
    o.x = *(uint32_t*)&h0; o.y = *(uint32_t*)&h1;
    o.z = *(uint32_t*)&h2; o.w = *(uint32_t*)&h3;
    *(uint4*)(E1 + threadIdx.x * 8) = o;
}

// ------------------- weight transpose fp16 (merged, z=weight) ---------------
__global__ void k_wh(const float* __restrict__ W0, const float* __restrict__ W1,
                     const float* __restrict__ W2, const float* __restrict__ W3,
                     const float* __restrict__ W4, const float* __restrict__ W5,
                     const float* __restrict__ W6, const float* __restrict__ W7,
                     const float* __restrict__ W8, __half* __restrict__ Tbase) {
    const float* Ws[9] = { W0, W1, W2, W3, W4, W5, W6, W7, W8 };
    const float* W = Ws[blockIdx.z];
    __half* Th = Tbase + (size_t)blockIdx.z * Hh * Hh;
    __shared__ float tile[32][33];
    int n0 = blockIdx.x << 5, k0 = blockIdx.y << 5;
    int tx = threadIdx.x, ty = threadIdx.y;
    for (int i = 0; i < 32; i += 8)
        tile[ty + i][tx] = W[(size_t)(k0 + ty + i) * Hh + n0 + tx];
    __syncthreads();
    for (int i = 0; i < 32; i += 8)
        Th[(size_t)(n0 + ty + i) * Hh + k0 + tx] = __float2half(tile[tx][ty + i]);
}

// ---------------- affinity transpose + hi/lo split (z=which) -----------------
__global__ void k_whl(const float* __restrict__ W0, const float* __restrict__ W1,
                      __half* __restrict__ ThB, __half* __restrict__ TlB) {
    const float* W = blockIdx.z ? W1 : W0;
    __half* Th = ThB + (size_t)blockIdx.z * Hh * Hh;
    __half* Tl = TlB + (size_t)blockIdx.z * Hh * Hh;
    __shared__ float tile[32][33];
    int n0 = blockIdx.x << 5, k0 = blockIdx.y << 5;
    int tx = threadIdx.x, ty = threadIdx.y;
    for (int i = 0; i < 32; i += 8)
        tile[ty + i][tx] = W[(size_t)(k0 + ty + i) * Hh + n0 + tx];
    __syncthreads();
    for (int i = 0; i < 32; i += 8) {
        float v = tile[tx][ty + i];
        __half h = __float2half(v);
        size_t o = (size_t)(n0 + ty + i) * Hh + k0 + tx;
        Th[o] = h;
        Tl[o] = __float2half(v - __half2float(h));
    }
}
__global__ void k_fh(const float* __restrict__ X0, const float* __restrict__ X1,
                     __half* __restrict__ H, int n) {
    int g = blockIdx.y;
    const float* X = g ? X1 : X0;
    int i = blockIdx.x * 256 + threadIdx.x;
    if (i < n) H[(size_t)g * n + i] = __float2half(X[i]);
}

// ---------------- layer-0 agg (merged graphs, 2 channels/thread) -------------
__global__ void k_agg0(const float* __restrict__ fe0, const float* __restrict__ fe1,
                       const int* __restrict__ esrc, const int* __restrict__ rowptr,
                       const int* __restrict__ colj, const float* __restrict__ aval,
                       const float* __restrict__ ew, const float* __restrict__ eb,
                       const float* __restrict__ ndx, const float* __restrict__ ndsx,
                       __half* __restrict__ oh) {
    __shared__ int   scol[Nn];
    __shared__ float sf[Nn];
    __shared__ float sa[Nn];
    int g = blockIdx.x >> 9;
    int r = blockIdx.x & 511;
    const float* fe = g ? fe1 : fe0;
    int b = r >> 6;
    int c = (blockIdx.y << 9) + threadIdx.x * 2;
    const int* rp = rowptr + g * (BN + 1);
    int s = rp[r], e = rp[r + 1];
    int n = e - s;
    if (threadIdx.x < n) {
        scol[threadIdx.x] = colj[g * MAXP + s + threadIdx.x];
        sf[threadIdx.x] = fe[esrc[g * MAXP + s + threadIdx.x]];
        sa[threadIdx.x] = aval[g * MAXP + s + threadIdx.x];
    }
    __syncthreads();
    const size_t MSZ = (size_t)BN * Hh;
    float2 w = *(const float2*)(ew + c);
    float2 bb = *(const float2*)(eb + c);
    float acc0 = 0.f, acc1 = 0.f;
    for (int q = 0; q < n; q++) {
        float2 nd = *(const float2*)(ndx + g * MSZ + (size_t)((b << 6) + scol[q]) * Hh + c);
        acc0 += sa[q] * (sf[q] * w.x + bb.x) * nd.x;
        acc1 += sa[q] * (sf[q] * w.y + bb.y) * nd.y;
    }
    float2 ns = *(const float2*)(ndsx + g * MSZ + (size_t)r * Hh + c);
    float v0 = fmaxf(acc0, 0.f) + fmaxf(ns.x, 0.f);
    float v1 = fmaxf(acc1, 0.f) + fmaxf(ns.y, 0.f);
    __half2 hv = __floats2half2_rn(v0, v1);
    *(__half2*)(oh + g * MSZ + (size_t)r * Hh + c) = hv;
}

// ---------------- agg with fp16 edges (merged, 2 ch/thread, +lo split) -------
__global__ void k_aggh(const __half* __restrict__ Ebase, const int* __restrict__ rowptr,
                       const int* __restrict__ colj, const float* __restrict__ aval,
                       const float* __restrict__ ndx, const float* __restrict__ ndsx,
                       float* __restrict__ embo, __half* __restrict__ oh,
                       __half* __restrict__ ol) {
    __shared__ int   scol[Nn];
    __shared__ float sa[Nn];
    int g = blockIdx.x >> 9;
    int r = blockIdx.x & 511;
    int b = r >> 6;
    int c = (blockIdx.y << 9) + threadIdx.x * 2;
    const int* rp = rowptr + g * (BN + 1);
    int s = rp[r], e = rp[r + 1];
    int n = e - s;
    if (threadIdx.x < n) {
        scol[threadIdx.x] = colj[g * MAXP + s + threadIdx.x];
        sa[threadIdx.x] = aval[g * MAXP + s + threadIdx.x];
    }
    __syncthreads();
    const size_t MSZ = (size_t)BN * Hh;
    const __half* E = Ebase + (size_t)g * 2 * ((size_t)MAXP * Hh);
    float acc0 = 0.f, acc1 = 0.f;
    for (int q = 0; q < n; q++) {
        __half2 ev = *(const __half2*)(E + (size_t)(s + q) * Hh + c);
        float2 nd = *(const float2*)(ndx + g * MSZ + (size_t)((b << 6) + scol[q]) * Hh + c);
        acc0 += sa[q] * __low2float(ev) * nd.x;
        acc1 += sa[q] * __high2float(ev) * nd.y;
    }
    float2 ns = *(const float2*)(ndsx + g * MSZ + (size_t)r * Hh + c);
    float v0 = fmaxf(acc0, 0.f) + fmaxf(ns.x, 0.f);
    float v1 = fmaxf(acc1, 0.f) + fmaxf(ns.y, 0.f);
    size_t o = g * MSZ + (size_t)r * Hh + c;
    if (embo) *(float2*)(embo + o) = make_float2(v0, v1);
    __half2 h2v = __floats2half2_rn(v0, v1);
    if (oh) *(__half2*)(oh + o) = h2v;
    if (ol) {
        float l0 = v0 - __half2float(__low2half(h2v));
        float l1 = v1 - __half2float(__high2half(h2v));
        *(__half2*)(ol + o) = __floats2half2_rn(l0, l1);
    }
}

// ---------------- U (merged): g=0: s@emb2 ; g=1: s^T@emb1 --------------------
__global__ void k_su(const float* __restrict__ S, const float* __restrict__ Emb1,
                     const float* __restrict__ Emb2, __half* __restrict__ Uh) {
    int idx = blockIdx.x;
    int g = idx >> 9;
    int blk = idx & 511;
    int b = blk >> 6, i = blk & 63;
    const float* Emb = g ? Emb1 : Emb2;
    __shared__ float srow[Nn];
    int t = threadIdx.x;
    if (t < Nn)
        srow[t] = g ? S[b * (Nn * Nn) + t * Nn + i]
                    : S[b * (Nn * Nn) + i * Nn + t];
    __syncthreads();
    const size_t MSZ = (size_t)BN * Hh;
    for (int c = t; c < Hh; c += 256) {
        float acc = 0.f;
#pragma unroll 8
        for (int j = 0; j < Nn; j++)
            acc += srow[j] * Emb[(size_t)((b << 6) + j) * Hh + c];
        Uh[g * MSZ + (size_t)blk * Hh + c] = __float2half(acc);
    }
}

// ------- fused affinity-bmm + sinkhorn: S = T[b]@E[b]^T, then sinkhorn -------
__global__ void __launch_bounds__(1024)
k_skb(const float* __restrict__ T, const float* __restrict__ E,
      float* __restrict__ out, const int* __restrict__ n1,
      const int* __restrict__ n2, const int* __restrict__ itp) {
    __shared__ float ls[64][65];
    __shared__ float Ts[64][33];
    __shared__ float Es[64][33];
    int b = blockIdx.x, t = threadIdx.x;
    int a1 = n1[b], a2 = n2[b];
    int tb = (a1 > a2);
    int nr = tb ? a2 : a1;
    int nc = tb ? a1 : a2;

    const float* Tb = T + (size_t)b * Nn * Hh;
    const float* Eb = E + (size_t)b * Nn * Hh;
    int rs = t >> 4;              // S row this thread owns (0..63)
    int cs = (t & 15) << 2;       // 4 S cols
    int lrow = t >> 4;            // load row (0..63)
    int lcol = (t & 15) << 1;     // load col pair
    float a0 = 0.f, a1f = 0.f, a2f = 0.f, a3f = 0.f;
    for (int kb = 0; kb < 32; kb++) {
        int k0 = kb << 5;
        float2 tv = *(const float2*)(Tb + (size_t)lrow * Hh + k0 + lcol);
        float2 ev = *(const float2*)(Eb + (size_t)lrow * Hh + k0 + lcol);
        __syncthreads();
        Ts[lrow][lcol] = tv.x; Ts[lrow][lcol + 1] = tv.y;
        Es[lrow][lcol] = ev.x; Es[lrow][lcol + 1] = ev.y;
        __syncthreads();
#pragma unroll
        for (int k = 0; k < 32; k++) {
            float av = Ts[rs][k];
            a0 += av * Es[cs + 0][k];
            a1f += av * Es[cs + 1][k];
            a2f += av * Es[cs + 2][k];
            a3f += av * Es[cs + 3][k];
        }
    }
    // stage into ls with transpose + mask (NEGV padding first)
    for (int e = t; e < 64 * 65; e += 1024) ((float*)ls)[e] = NEGV;
    __syncthreads();
    float vv[4] = { a0, a1f, a2f, a3f };
#pragma unroll
    for (int j = 0; j < 4; j++) {
        int c_s = cs + j;
        int rr = tb ? c_s : rs;
        int cc = tb ? rs : c_s;
        if (rr < nr && cc < nc) ls[rr][cc] = vv[j] / 0.05f;
    }
    __syncthreads();

    int iters = *itp;
    int w = t >> 5, lane = t & 31;   // 32 warps
    for (int it = 0; it < iters; it++) {
        if ((it & 1) == 0) {
            for (int r = w; r < 64; r += 32) {
                float x0 = ls[r][lane], x1 = ls[r][lane + 32];
                float m = fmaxf(x0, x1);
                for (int o = 16; o; o >>= 1) m = fmaxf(m, __shfl_xor_sync(0xffffffffu, m, o));
                float sm = expf(x0 - m) + expf(x1 - m);
                for (int o = 16; o; o >>= 1) sm += __shfl_xor_sync(0xffffffffu, sm, o);
                float lse = m + logf(sm);
                bool rm = (r < nr);
                ls[r][lane]      = (rm && lane < nc)        ? x0 - lse : NEGV;
                ls[r][lane + 32] = (rm && (lane + 32) < nc) ? x1 - lse : NEGV;
            }
        } else {
            for (int c = w; c < 64; c += 32) {
                float x0 = ls[lane][c], x1 = ls[lane + 32][c];
                float m = fmaxf(x0, x1);
                for (int o = 16; o; o >>= 1) m = fmaxf(m, __shfl_xor_sync(0xffffffffu, m, o));
                float sm = expf(x0 - m) + expf(x1 - m);
                for (int o = 16; o; o >>= 1) sm += __shfl_xor_sync(0xffffffffu, sm, o);
                float lse = m + logf(sm);
                bool cm = (c < nc);
                ls[lane][c]      = (cm && lane < nr)        ? x0 - lse : NEGV;
                ls[lane + 32][c] = (cm && (lane + 32) < nr) ? x1 - lse : NEGV;
            }
        }
        __syncthreads();
    }
    for (int e = t; e < 4096; e += 1024) {
        int r = e >> 6, c = e & 63;
        float v = (r < nr && c < nc) ? expf(ls[r][c]) : 0.f;
        if (tb) out[b * 4096 + c * 64 + r] = v;
        else    out[b * 4096 + r * 64 + c] = v;
    }
}

// ------------------------------- launch --------------------------------------
extern "C" void kernel_launch(void* const* d_in, const int* in_sizes, int n_in,
                              void* d_out, int out_size) {
    (void)in_sizes; (void)n_in; (void)out_size;
    const float* fn[2]   = { (const float*)d_in[0], (const float*)d_in[1] };
    const float* Aadj[2] = { (const float*)d_in[2], (const float*)d_in[3] };
    const float* fe[2]   = { (const float*)d_in[4], (const float*)d_in[5] };
    const float* lw[3][6];
    for (int l = 0; l < 3; l++)
        for (int k = 0; k < 6; k++)
            lw[l][k] = (const float*)d_in[6 + l * 6 + k];
    const float* aff1 = (const float*)d_in[24];
    const float* aff2 = (const float*)d_in[25];
    const float* cw   = (const float*)d_in[26];
    const float* cb   = (const float*)d_in[27];
    const int*   n1   = (const int*)d_in[28];
    const int*   n2   = (const int*)d_in[29];
    const int*   itp  = (const int*)d_in[30];
    float* out = (float*)d_out;

    void* p;
    cudaGetSymbolAddress(&p, g_Ehp);    __half* Ehp   = (__half*)p;
    cudaGetSymbolAddress(&p, g_emb32);  float*  emb32 = (float*)p;
    cudaGetSymbolAddress(&p, g_embh);   __half* ebh   = (__half*)p;
    cudaGetSymbolAddress(&p, g_embl);   __half* ebl   = (__half*)p;
    cudaGetSymbolAddress(&p, g_ndx);    float*  ndx   = (float*)p;
    cudaGetSymbolAddress(&p, g_ndsx);   float*  ndsx  = (float*)p;
    cudaGetSymbolAddress(&p, g_t);      float*  tbuf  = (float*)p;
    cudaGetSymbolAddress(&p, g_uh);     __half* uh    = (__half*)p;
    cudaGetSymbolAddress(&p, g_fnh);    __half* fnh   = (__half*)p;
    cudaGetSymbolAddress(&p, g_wth);    __half* wth   = (__half*)p;
    cudaGetSymbolAddress(&p, g_afh);    __half* afh   = (__half*)p;
    cudaGetSymbolAddress(&p, g_afl);    __half* afl   = (__half*)p;
    cudaGetSymbolAddress(&p, g_alpha);  float*  alpha = (float*)p;
    cudaGetSymbolAddress(&p, g_beta);   float*  beta  = (float*)p;
    cudaGetSymbolAddress(&p, g_bt);     float*  bt    = (float*)p;
    cudaGetSymbolAddress(&p, g_bc);     int*    bc    = (int*)p;
    cudaGetSymbolAddress(&p, g_b0a);    float*  b0a   = (float*)p;
    cudaGetSymbolAddress(&p, g_b0b);    float*  b0b   = (float*)p;
    cudaGetSymbolAddress(&p, g_da);     float*  da    = (float*)p;
    cudaGetSymbolAddress(&p, g_db);     float*  db    = (float*)p;
    cudaGetSymbolAddress(&p, g_offa);   float*  offa  = (float*)p;
    cudaGetSymbolAddress(&p, g_offb);   float*  offb  = (float*)p;
    cudaGetSymbolAddress(&p, g_ssk);    float*  ssk   = (float*)p;
    cudaGetSymbolAddress(&p, g_rowcnt); int* rowcnt   = (int*)p;
    cudaGetSymbolAddress(&p, g_rowptr); int* rowptr   = (int*)p;
    cudaGetSymbolAddress(&p, g_colj);   int* colj     = (int*)p;
    cudaGetSymbolAddress(&p, g_esrc);   int* esrc     = (int*)p;
    cudaGetSymbolAddress(&p, g_aval);   float* aval   = (float*)p;
    cudaGetSymbolAddress(&p, g_cnt);    int* cnt      = (int*)p;

    const size_t ESZ = (size_t)MAXP * Hh;
    const size_t MSZ = (size_t)BN * Hh;
    const size_t WSZ = (size_t)Hh * Hh;
#define E1P(g)     (Ehp + ((size_t)(g) * 2 + 0) * ESZ)
#define M32(g)     (emb32 + (size_t)(g) * MSZ)
#define EBH(pp, g) (ebh + ((size_t)(pp) * 2 + (g)) * MSZ)
#define WH(i)      (wth + (size_t)(i) * WSZ)

    cudaStream_t s0 = 0;
    cudaStream_t s2 = g_si.s2;

    // ---- fork ----
    cudaEventRecord(g_si.evRoot, s0);
    cudaStreamWaitEvent(s2, g_si.evRoot, 0);

    // ---- side stream: PWL table first (gates pwl -> E2), whl slotted after --
    k_sort<<<1, 1024, 0, s2>>>(lw[0][4], lw[0][5], bt, bc);
    k_bd<<<dim3(8, 16, 2), 128, 0, s2>>>(lw[0][4], lw[0][5], lw[1][4], lw[1][5], bc,
                                         b0a, b0b, da, db);
    k_offs<<<8, 128, 0, s2>>>(b0a, b0b, da, db, offa, offb, alpha, beta);
    k_fillscan<<<dim3(8, 16), 128, 0, s2>>>(lw[0][4], lw[0][5], lw[1][4], bc,
                                            offa, offb, alpha, beta);

    // ---- main stream: weights + features + compaction ----
    k_wh<<<dim3(32, 32, 9), dim3(32, 8), 0, s0>>>(lw[0][0], lw[0][2], lw[1][0], lw[1][2],
                                                  lw[2][0], lw[2][2], lw[2][4], cw,
                                                  cw + WSZ, wth);
    cudaEventRecord(g_si.evW, s0);              // weights ready (for E2 GEMM on s2)
    k_fh<<<dim3((int)(MSZ / 256), 2), 256, 0, s0>>>(fn[0], fn[1], fnh, (int)MSZ);
    k_count<<<dim3(8, 2), 64, 0, s0>>>(Aadj[0], Aadj[1], rowcnt);
    k_scan<<<2, BN, 0, s0>>>(rowcnt, rowptr, cnt);
    k_fill<<<dim3(8, 2), 64, 0, s0>>>(Aadj[0], Aadj[1], rowptr, colj, esrc, aval);
    cudaEventRecord(g_si.evA, s0);              // compaction ready

    // ---- side stream: E1 eval, affinity splits, E2 GEMM ----
    cudaStreamWaitEvent(s2, g_si.evA, 0);
    k_pwl<<<dim3(MAXP, 2), 128, 0, s2>>>(fe[0], fe[1], esrc, cnt, bt, alpha, beta, Ehp);
    cudaEventRecord(g_si.evB, s2);              // E1 ready
    k_whl<<<dim3(32, 32, 2), dim3(32, 8), 0, s2>>>(aff1, aff2, afh, afl);
    cudaEventRecord(g_si.evE, s2);              // aff splits ready
    cudaStreamWaitEvent(s2, g_si.evW, 0);
    k_h16<<<dim3(256, 8, 2), 256, 0, s2>>>(E1P(0), E1P(1), WH(6), lw[2][5],
                                           Ehp + ESZ, Ehp + 3 * ESZ, cnt);
    cudaEventRecord(g_si.evD, s2);              // E2 ready

    // ---- main stream: node layers 0-1 (fp32 acc) ----
    k_hgemm<<<dim3(8, 8, 2), 256, 0, s0>>>(fnh, nullptr, nullptr, nullptr,
                                           WH(0), WH(1), nullptr, nullptr,
                                           lw[0][1], lw[0][3], ndx, ndsx,
                                           nullptr, nullptr, 0, 0, 0, 2 * BN, nullptr);
    k_agg0<<<dim3(1024, 2), 256, 0, s0>>>(fe[0], fe[1], esrc, rowptr, colj, aval,
                                          lw[0][4], lw[0][5], ndx, ndsx, EBH(0, 0));
    k_hgemm<<<dim3(8, 8, 2), 256, 0, s0>>>(EBH(0, 0), nullptr, nullptr, nullptr,
                                           WH(2), WH(3), nullptr, nullptr,
                                           lw[1][1], lw[1][3], ndx, ndsx,
                                           nullptr, nullptr, 0, 0, 0, 2 * BN, nullptr);
    cudaStreamWaitEvent(s0, g_si.evB, 0);
    k_aggh<<<dim3(1024, 2), 256, 0, s0>>>(E1P(0), rowptr, colj, aval, ndx, ndsx,
                                          M32(0), EBH(1, 0), ebl);
    // ---- cross-attention mid-section (overlaps E2 GEMM on s2) ----
    cudaStreamWaitEvent(s0, g_si.evE, 0);       // need aff splits
    k_hgemm<<<dim3(4, 8, 1), 256, 0, s0>>>(EBH(1, 0), nullptr, EBH(1, 0), ebl,
                                           afh, nullptr, afl, afh,
                                           nullptr, nullptr, tbuf, nullptr,
                                           nullptr, nullptr, 0, 0, 0, BN, nullptr);
    k_skb<<<8, 1024, 0, s0>>>(tbuf, M32(1), ssk, n1, n2, itp);
    k_su<<<1024, 256, 0, s0>>>(ssk, M32(0), M32(1), uh);
    k_hgemm<<<dim3(8, 8, 1), 256, 0, s0>>>(EBH(1, 0), nullptr, uh, nullptr,
                                           WH(7), nullptr, WH(8), nullptr,
                                           cb, nullptr, nullptr, nullptr,
                                           EBH(0, 0), nullptr, 0, 0, 0, 2 * BN, nullptr);
    k_hgemm<<<dim3(8, 8, 2), 256, 0, s0>>>(EBH(0, 0), nullptr, nullptr, nullptr,
                                           WH(4), WH(5), nullptr, nullptr,
                                           lw[2][1], lw[2][3], ndx, ndsx,
                                           nullptr, nullptr, 0, 0, 0, 2 * BN, nullptr);
    // ---- join: layer-2 agg needs E2; M32 write REQUIRED (final skb reads it) -
    cudaStreamWaitEvent(s0, g_si.evD, 0);
    k_aggh<<<dim3(1024, 2), 256, 0, s0>>>(Ehp + ESZ, rowptr, colj, aval, ndx, ndsx,
                                          M32(0), EBH(1, 0), ebl);
    // ---- final affinity + fused bmm/sinkhorn ----
    k_hgemm<<<dim3(4, 8, 1), 256, 0, s0>>>(EBH(1, 0), nullptr, EBH(1, 0), ebl,
                                           afh + WSZ, nullptr, afl + WSZ, afh + WSZ,
                                           nullptr, nullptr, tbuf, nullptr,
                                           nullptr, nullptr, 0, 0, 0, BN, nullptr);
    k_skb<<<8, 1024, 0, s0>>>(tbuf, M32(1), out, n1, n2, itp);
#undef E1P
#undef M32
#undef EBH
#undef WH
}

// round 16
// speedup vs baseline: 1.1304x; 1.1304x over previous
#include <cuda_runtime.h>
#include <cuda_fp16.h>
#include <math.h>
#include <stdint.h>

#define Bb   8
#define Nn   64
#define Hh   1024
#define BN   512
#define MAXP 32768
#define NEGV -1e30f

// ------------------------------- scratch ------------------------------------
__device__ __half g_Ehp[2][2][(size_t)MAXP * Hh];   // [graph][{E1pre, E2pre}] fp16
__device__ float  g_emb32[2][(size_t)BN * Hh];
__device__ __half g_embh[4][(size_t)BN * Hh];       // [pp*2+g]
__device__ __half g_embl[2][(size_t)BN * Hh];       // lo split of current emb
__device__ float  g_ndx[2][(size_t)BN * Hh];
__device__ float  g_ndsx[2][(size_t)BN * Hh];
__device__ float  g_t[(size_t)BN * Hh];
__device__ __half g_uh[2][(size_t)BN * Hh];
__device__ __half g_fnh[2][(size_t)BN * Hh];
__device__ __half g_wth[9][(size_t)Hh * Hh];
__device__ __half g_afh[2][(size_t)Hh * Hh];        // aff^T hi
__device__ __half g_afl[2][(size_t)Hh * Hh];        // aff^T lo
__device__ float  g_alpha[(size_t)1025 * Hh];
__device__ float  g_beta[(size_t)1025 * Hh];
__device__ float  g_bt[1024];
__device__ int    g_bc[1024];
__device__ float  g_b0a[16 * 1024], g_b0b[16 * 1024];
__device__ float  g_da[16 * 1024],  g_db[16 * 1024];
__device__ float  g_offa[16 * 1024], g_offb[16 * 1024];
__device__ float  g_spart[4 * Bb * Nn * Nn];
__device__ float  g_ssk[Bb * Nn * Nn];
__device__ int    g_rowcnt[2][BN];
__device__ int    g_rowptr[2][BN + 1];
__device__ int    g_colj[2][MAXP];
__device__ int    g_esrc[2][MAXP];
__device__ float  g_aval[2][MAXP];
__device__ int    g_cnt[2];

// ---- streams/events created at static-init ----------------------------------
struct GInit {
    cudaStream_t s2;
    cudaEvent_t evRoot, evA, evW, evB, evD, evE;
    GInit() {
        cudaStreamCreateWithFlags(&s2, cudaStreamNonBlocking);
        cudaEventCreateWithFlags(&evRoot, cudaEventDisableTiming);
        cudaEventCreateWithFlags(&evA, cudaEventDisableTiming);
        cudaEventCreateWithFlags(&evW, cudaEventDisableTiming);
        cudaEventCreateWithFlags(&evB, cudaEventDisableTiming);
        cudaEventCreateWithFlags(&evD, cudaEventDisableTiming);
        cudaEventCreateWithFlags(&evE, cudaEventDisableTiming);
    }
};
static GInit g_si;

// ------------------------------- helpers ------------------------------------
__device__ __forceinline__ uint32_t smem_u32(const void* p) {
    uint32_t a;
    asm("{ .reg .u64 t; cvta.to.shared.u64 t, %1; cvt.u32.u64 %0, t; }" : "=r"(a) : "l"(p));
    return a;
}
#define MMA16816(d, a, b) \
    asm volatile("mma.sync.aligned.m16n8k16.row.col.f32.f16.f16.f32 " \
        "{%0,%1,%2,%3}, {%4,%5,%6,%7}, {%8,%9}, {%0,%1,%2,%3};" \
        : "+f"((d)[0]), "+f"((d)[1]), "+f"((d)[2]), "+f"((d)[3]) \
        : "r"((a)[0]), "r"((a)[1]), "r"((a)[2]), "r"((a)[3]), \
          "r"((b)[0]), "r"((b)[1]))
#define MMA16816H(d, a, b) \
    asm volatile("mma.sync.aligned.m16n8k16.row.col.f16.f16.f16.f16 " \
        "{%0,%1}, {%2,%3,%4,%5}, {%6,%7}, {%0,%1};" \
        : "+r"((d)[0]), "+r"((d)[1]) \
        : "r"((a)[0]), "r"((a)[1]), "r"((a)[2]), "r"((a)[3]), \
          "r"((b)[0]), "r"((b)[1]))
#define LDSM4(r0, r1, r2, r3, addr) \
    asm volatile("ldmatrix.sync.aligned.m8n8.x4.shared.b16 {%0,%1,%2,%3}, [%4];" \
        : "=r"(r0), "=r"(r1), "=r"(r2), "=r"(r3) : "r"(addr))
#define CPA16(dst, src, nbytes) \
    asm volatile("cp.async.ca.shared.global [%0], [%1], 16, %2;" \
        :: "r"(dst), "l"(src), "r"(nbytes))
#define CPA_COMMIT() asm volatile("cp.async.commit_group;")
#define CPA_WAIT0()  asm volatile("cp.async.wait_group 0;")

// ---------------- fp32-accumulate GEMM (node/cross/affinity) -----------------
__global__ void __launch_bounds__(256, 2)
k_hgemm(const __half* __restrict__ A0, const __half* __restrict__ A1g,
        const __half* __restrict__ A2, const __half* __restrict__ A3,
        const __half* __restrict__ B0, const __half* __restrict__ B1,
        const __half* __restrict__ B2, const __half* __restrict__ B3,
        const float* __restrict__ bias0, const float* __restrict__ bias1,
        float* __restrict__ C0, float* __restrict__ C1z,
        __half* __restrict__ Oh0, __half* __restrict__ Oh1g,
        int relu_a, int relu_oh, int zmode,
        int M, const int* __restrict__ Mptr)
{
    int z = blockIdx.z;
    const __half* A = A0;
    const __half* Bsel = B0;
    const float* bias = bias0;
    float* C = C0;
    __half* Oh = Oh0;
    if (zmode == 0) {
        if (Mptr) M = *Mptr;
        if (z == 1) { Bsel = B1; bias = bias1; C = C1z; Oh = nullptr; }
    } else {
        M = Mptr[z];
        if (z == 1) { A = A1g; Oh = Oh1g; C = C1z; }
    }
    int m0 = blockIdx.x << 7;
    if (m0 >= M) return;
    int n0 = blockIdx.y << 7;

    __shared__ __align__(16) char smraw[40960];
    uint32_t sb = smem_u32(smraw);
    const uint32_t STG = 2 * 128 * 40 * 2;
    const uint32_t OPS = 128 * 40 * 2;

    int t = threadIdx.x, lane = t & 31, wid = t >> 5;
    int wm = wid & 3, wn = wid >> 2;

    int lrow = t >> 1;
    int lhalf = (t & 1) << 4;
    size_t aoff = (size_t)(m0 + lrow) * Hh + lhalf;
    size_t boff = (size_t)(n0 + lrow) * Hh + lhalf;
    int abytes = (m0 + lrow < M) ? 16 : 0;
    uint32_t ldst = (uint32_t)(lrow * 40 + lhalf) * 2;

    float acc[2][8][4];
#pragma unroll
    for (int i = 0; i < 2; i++)
#pragma unroll
        for (int j = 0; j < 8; j++)
#pragma unroll
            for (int k = 0; k < 4; k++) acc[i][j][k] = 0.f;

    const __half* PA[3] = { A, A2, A3 };
    const __half* PB[3] = { Bsel, B2, B3 };
    int npairs = A3 ? 3 : (A2 ? 2 : 1);
    int T = npairs << 5;

    auto prefetch = [&](int it, int stg) {
        int pr = it >> 5;
        const __half* pA = PA[pr] + aoff + ((it & 31) << 5);
        const __half* pB = PB[pr] + boff + ((it & 31) << 5);
        uint32_t dA = sb + (uint32_t)stg * STG + ldst;
        CPA16(dA, pA, abytes);
        CPA16(dA + 16, pA + 8, abytes);
        uint32_t dB = dA + OPS;
        CPA16(dB, pB, 16);
        CPA16(dB + 16, pB + 8, 16);
        CPA_COMMIT();
    };

    prefetch(0, 0);
    int fr = lane & 15;
    int fk = (lane >> 4) << 3;
    const __half2 z2 = __float2half2_rn(0.f);

    for (int it = 0; it < T; it++) {
        CPA_WAIT0();
        __syncthreads();
        if (it + 1 < T) prefetch(it + 1, (it + 1) & 1);
        uint32_t stage = sb + (uint32_t)(it & 1) * STG;
#pragma unroll
        for (int ks = 0; ks < 2; ks++) {
            int kc = ks << 4;
            uint32_t af[2][4];
#pragma unroll
            for (int mt = 0; mt < 2; mt++) {
                uint32_t addr = stage + (uint32_t)((wm * 32 + mt * 16 + fr) * 40 + kc + fk) * 2;
                LDSM4(af[mt][0], af[mt][1], af[mt][2], af[mt][3], addr);
                if (relu_a) {
#pragma unroll
                    for (int q = 0; q < 4; q++) {
                        __half2 h = *(__half2*)&af[mt][q];
                        h = __hmax2(h, z2);
                        af[mt][q] = *(uint32_t*)&h;
                    }
                }
            }
            uint32_t bf[8][2];
#pragma unroll
            for (int nq = 0; nq < 4; nq++) {
                uint32_t r0, r1, r2, r3;
                uint32_t addr = stage + OPS +
                    (uint32_t)((wn * 64 + nq * 16 + fr) * 40 + kc + fk) * 2;
                LDSM4(r0, r1, r2, r3, addr);
                bf[nq * 2][0] = r0; bf[nq * 2][1] = r2;
                bf[nq * 2 + 1][0] = r1; bf[nq * 2 + 1][1] = r3;
            }
#pragma unroll
            for (int mt = 0; mt < 2; mt++)
#pragma unroll
                for (int nt = 0; nt < 8; nt++)
                    MMA16816(acc[mt][nt], af[mt], bf[nt]);
        }
    }

    float* ssm = (float*)smraw;
#pragma unroll
    for (int half = 0; half < 2; half++) {
        __syncthreads();
        if (wn == half) {
#pragma unroll
            for (int mt = 0; mt < 2; mt++)
#pragma unroll
                for (int nt = 0; nt < 8; nt++) {
                    int r = wm * 32 + mt * 16 + (lane >> 2);
                    int cl = nt * 8 + ((lane & 3) << 1);
                    ssm[r * 68 + cl]           = acc[mt][nt][0];
                    ssm[r * 68 + cl + 1]       = acc[mt][nt][1];
                    ssm[(r + 8) * 68 + cl]     = acc[mt][nt][2];
                    ssm[(r + 8) * 68 + cl + 1] = acc[mt][nt][3];
                }
        }
        __syncthreads();
        int r = t >> 1, cl = (t & 1) << 5;
        if (m0 + r < M) {
            int gc = n0 + half * 64 + cl;
            size_t gb = (size_t)(m0 + r) * Hh + gc;
#pragma unroll
            for (int i = 0; i < 8; i++) {
                float4 v = *(float4*)&ssm[r * 68 + cl + i * 4];
                if (bias) {
                    float4 bv = *(const float4*)(bias + gc + i * 4);
                    v.x += bv.x; v.y += bv.y; v.z += bv.z; v.w += bv.w;
                }
                if (C) *(float4*)&C[gb + i * 4] = v;
                if (Oh) {
                    float v0 = v.x, v1 = v.y, v2 = v.z, v3 = v.w;
                    if (relu_oh) {
                        v0 = fmaxf(v0, 0.f); v1 = fmaxf(v1, 0.f);
                        v2 = fmaxf(v2, 0.f); v3 = fmaxf(v3, 0.f);
                    }
                    __half2 h01 = __floats2half2_rn(v0, v1);
                    __half2 h23 = __floats2half2_rn(v2, v3);
                    *(uint2*)&Oh[gb + i * 4] =
                        make_uint2(*(uint32_t*)&h01, *(uint32_t*)&h23);
                }
            }
        }
    }
}

// ---------------- fp16-accumulate GEMM (edge E2 ONLY — proven safe + faster) -
__global__ void __launch_bounds__(256, 2)
k_h16(const __half* __restrict__ A0, const __half* __restrict__ A1g,
      const __half* __restrict__ B0, const float* __restrict__ bias,
      __half* __restrict__ Oh0, __half* __restrict__ Oh1g,
      const int* __restrict__ Mptr)
{
    int z = blockIdx.z;
    const __half* A = z ? A1g : A0;
    __half* Oh = z ? Oh1g : Oh0;
    int M = Mptr[z];
    int m0 = blockIdx.x << 7;
    if (m0 >= M) return;
    int n0 = blockIdx.y << 7;

    __shared__ __align__(16) char smraw[40960];
    uint32_t sb = smem_u32(smraw);
    const uint32_t STG = 2 * 128 * 40 * 2;
    const uint32_t OPS = 128 * 40 * 2;

    int t = threadIdx.x, lane = t & 31, wid = t >> 5;
    int wm = wid & 3, wn = wid >> 2;

    int lrow = t >> 1;
    int lhalf = (t & 1) << 4;
    size_t aoff = (size_t)(m0 + lrow) * Hh + lhalf;
    size_t boff = (size_t)(n0 + lrow) * Hh + lhalf;
    int abytes = (m0 + lrow < M) ? 16 : 0;
    uint32_t ldst = (uint32_t)(lrow * 40 + lhalf) * 2;

    uint32_t acc[2][8][2];
#pragma unroll
    for (int i = 0; i < 2; i++)
#pragma unroll
        for (int j = 0; j < 8; j++) { acc[i][j][0] = 0u; acc[i][j][1] = 0u; }

    auto prefetch = [&](int it, int stg) {
        int ko = it << 5;
        const __half* pA = A + aoff + ko;
        const __half* pB = B0 + boff + ko;
        uint32_t dA = sb + (uint32_t)stg * STG + ldst;
        CPA16(dA, pA, abytes);
        CPA16(dA + 16, pA + 8, abytes);
        uint32_t dB = dA + OPS;
        CPA16(dB, pB, 16);
        CPA16(dB + 16, pB + 8, 16);
        CPA_COMMIT();
    };

    prefetch(0, 0);
    int fr = lane & 15;
    int fk = (lane >> 4) << 3;
    const __half2 z2 = __float2half2_rn(0.f);

    for (int it = 0; it < 32; it++) {
        CPA_WAIT0();
        __syncthreads();
        if (it + 1 < 32) prefetch(it + 1, (it + 1) & 1);
        uint32_t stage = sb + (uint32_t)(it & 1) * STG;
#pragma unroll
        for (int ks = 0; ks < 2; ks++) {
            int kc = ks << 4;
            uint32_t af[2][4];
#pragma unroll
            for (int mt = 0; mt < 2; mt++) {
                uint32_t addr = stage + (uint32_t)((wm * 32 + mt * 16 + fr) * 40 + kc + fk) * 2;
                LDSM4(af[mt][0], af[mt][1], af[mt][2], af[mt][3], addr);
#pragma unroll
                for (int q = 0; q < 4; q++) {
                    __half2 h = *(__half2*)&af[mt][q];
                    h = __hmax2(h, z2);
                    af[mt][q] = *(uint32_t*)&h;
                }
            }
            uint32_t bf[8][2];
#pragma unroll
            for (int nq = 0; nq < 4; nq++) {
                uint32_t r0, r1, r2, r3;
                uint32_t addr = stage + OPS +
                    (uint32_t)((wn * 64 + nq * 16 + fr) * 40 + kc + fk) * 2;
                LDSM4(r0, r1, r2, r3, addr);
                bf[nq * 2][0] = r0; bf[nq * 2][1] = r2;
                bf[nq * 2 + 1][0] = r1; bf[nq * 2 + 1][1] = r3;
            }
#pragma unroll
            for (int mt = 0; mt < 2; mt++)
#pragma unroll
                for (int nt = 0; nt < 8; nt++)
                    MMA16816H(acc[mt][nt], af[mt], bf[nt]);
        }
    }

    float* ssm = (float*)smraw;
#pragma unroll
    for (int half = 0; half < 2; half++) {
        __syncthreads();
        if (wn == half) {
#pragma unroll
            for (int mt = 0; mt < 2; mt++)
#pragma unroll
                for (int nt = 0; nt < 8; nt++) {
                    int r = wm * 32 + mt * 16 + (lane >> 2);
                    int cl = nt * 8 + ((lane & 3) << 1);
                    __half2 p0 = *(__half2*)&acc[mt][nt][0];
                    __half2 p1 = *(__half2*)&acc[mt][nt][1];
                    ssm[r * 68 + cl]           = __low2float(p0);
                    ssm[r * 68 + cl + 1]       = __high2float(p0);
                    ssm[(r + 8) * 68 + cl]     = __low2float(p1);
                    ssm[(r + 8) * 68 + cl + 1] = __high2float(p1);
                }
        }
        __syncthreads();
        int r = t >> 1, cl = (t & 1) << 5;
        if (m0 + r < M) {
            int gc = n0 + half * 64 + cl;
            size_t gb = (size_t)(m0 + r) * Hh + gc;
#pragma unroll
            for (int i = 0; i < 8; i++) {
                float4 v = *(float4*)&ssm[r * 68 + cl + i * 4];
                float4 bv = *(const float4*)(bias + gc + i * 4);
                v.x += bv.x; v.y += bv.y; v.z += bv.z; v.w += bv.w;
                __half2 h01 = __floats2half2_rn(v.x, v.y);
                __half2 h23 = __floats2half2_rn(v.z, v.w);
                *(uint2*)&Oh[gb + i * 4] =
                    make_uint2(*(uint32_t*)&h01, *(uint32_t*)&h23);
            }
        }
    }
}

// ------------------------- compaction (merged graphs) -----------------------
__global__ void k_count(const float* __restrict__ A0, const float* __restrict__ A1,
                        int* __restrict__ rowcnt) {
    int g = blockIdx.y;
    const float* A = g ? A1 : A0;
    int r = blockIdx.x * 64 + threadIdx.x;
    const float* row = A + (size_t)r * Nn;
    int c = 0;
    for (int j = 0; j < Nn; j++) c += (row[j] != 0.0f);
    rowcnt[g * BN + r] = c;
}
__global__ void k_scan(const int* __restrict__ rowcnt, int* __restrict__ rowptr,
                       int* __restrict__ cnt) {
    __shared__ int sm[BN];
    int g = blockIdx.x, t = threadIdx.x;
    sm[t] = rowcnt[g * BN + t];
    __syncthreads();
    for (int off = 1; off < BN; off <<= 1) {
        int v = (t >= off) ? sm[t - off] : 0;
        __syncthreads();
        sm[t] += v;
        __syncthreads();
    }
    rowptr[g * (BN + 1) + t + 1] = sm[t];
    if (t == 0)      rowptr[g * (BN + 1)] = 0;
    if (t == BN - 1) cnt[g] = sm[BN - 1];
}
__global__ void k_fill(const float* __restrict__ A0, const float* __restrict__ A1,
                       const int* __restrict__ rowptr,
                       int* __restrict__ colj, int* __restrict__ esrc,
                       float* __restrict__ aval) {
    int g = blockIdx.y;
    const float* A = g ? A1 : A0;
    int r = blockIdx.x * 64 + threadIdx.x;
    const float* row = A + (size_t)r * Nn;
    int pos = rowptr[g * (BN + 1) + r];
    for (int j = 0; j < Nn; j++) {
        float a = row[j];
        if (a != 0.0f) {
            colj[g * MAXP + pos] = j;
            esrc[g * MAXP + pos] = r * Nn + j;
            aval[g * MAXP + pos] = a;
            pos++;
        }
    }
}

// ---------------- PWL: sort breakpoints (bitonic, 1 block) ------------------
__global__ void k_sort(const float* __restrict__ ew, const float* __restrict__ eb,
                       float* __restrict__ bt, int* __restrict__ bc) {
    __shared__ float sk[1024];
    __shared__ int   sc[1024];
    int t = threadIdx.x;
    float e = ew[t];
    sk[t] = (e != 0.f) ? (-eb[t] / e) : 3.4e38f;
    sc[t] = t;
    __syncthreads();
    for (int k = 2; k <= 1024; k <<= 1) {
        for (int j = k >> 1; j > 0; j >>= 1) {
            int ixj = t ^ j;
            if (ixj > t) {
                float a = sk[t], b = sk[ixj];
                int ca = sc[t], cb = sc[ixj];
                bool gt = (a > b) || (a == b && ca > cb);
                bool up = ((t & k) == 0);
                if (gt == up) { sk[t] = b; sk[ixj] = a; sc[t] = cb; sc[ixj] = ca; }
            }
            __syncthreads();
        }
    }
    bt[t] = sk[t];
    bc[t] = sc[t];
}

// ---------------- PWL: base partials + delta sums (merged, MLP=4) -----------
__global__ void k_bd(const float* __restrict__ ew, const float* __restrict__ eb,
                     const float* __restrict__ W1, const float* __restrict__ b1,
                     const int* __restrict__ bc,
                     float* __restrict__ b0a, float* __restrict__ b0b,
                     float* __restrict__ da, float* __restrict__ db) {
    int col = blockIdx.x * 128 + threadIdx.x;
    int ch = blockIdx.y;
    if (blockIdx.z == 0) {
        float a = 0.f, b = (ch == 0) ? b1[col] : 0.f;
        for (int qb = 0; qb < 64; qb += 4) {
            float e[4], ebv[4], w[4];
#pragma unroll
            for (int i = 0; i < 4; i++) {
                int c = ch * 64 + qb + i;
                e[i] = ew[c]; ebv[i] = eb[c];
                w[i] = __ldg(&W1[(size_t)c * Hh + col]);
            }
#pragma unroll
            for (int i = 0; i < 4; i++) {
                if (e[i] < 0.f) { a += e[i] * w[i]; b += ebv[i] * w[i]; }
                else if (e[i] == 0.f && ebv[i] > 0.f) b += ebv[i] * w[i];
            }
        }
        b0a[ch * 1024 + col] = a;
        b0b[ch * 1024 + col] = b;
    } else {
        float a = 0.f, b = 0.f;
        for (int qb = 0; qb < 64; qb += 4) {
            float e[4], ebv[4], w[4];
#pragma unroll
            for (int i = 0; i < 4; i++) {
                int c = bc[ch * 64 + qb + i];
                e[i] = ew[c]; ebv[i] = eb[c];
                w[i] = __ldg(&W1[(size_t)c * Hh + col]);
            }
#pragma unroll
            for (int i = 0; i < 4; i++) {
                float s = (e[i] > 0.f) ? 1.f : ((e[i] < 0.f) ? -1.f : 0.f);
                a += s * e[i] * w[i];
                b += s * ebv[i] * w[i];
            }
        }
        da[ch * 1024 + col] = a;
        db[ch * 1024 + col] = b;
    }
}

// ---------------- PWL: chunk offsets + segment-0 row -------------------------
__global__ void k_offs(const float* __restrict__ b0a, const float* __restrict__ b0b,
                       const float* __restrict__ da, const float* __restrict__ db,
                       float* __restrict__ offa, float* __restrict__ offb,
                       float* __restrict__ alpha, float* __restrict__ beta) {
    int col = blockIdx.x * 128 + threadIdx.x;
    float a = 0.f, b = 0.f;
#pragma unroll
    for (int cc = 0; cc < 16; cc++) { a += b0a[cc * 1024 + col]; b += b0b[cc * 1024 + col]; }
    alpha[col] = a;
    beta[col] = b;
#pragma unroll
    for (int jc = 0; jc < 16; jc++) {
        offa[jc * 1024 + col] = a;
        offb[jc * 1024 + col] = b;
        a += da[jc * 1024 + col];
        b += db[jc * 1024 + col];
    }
}

// ---------------- PWL: fill rows 1..1024 (prefetch 4) ------------------------
__global__ void k_fillscan(const float* __restrict__ ew, const float* __restrict__ eb,
                           const float* __restrict__ W1, const int* __restrict__ bc,
                           const float* __restrict__ offa, const float* __restrict__ offb,
                           float* __restrict__ alpha, float* __restrict__ beta) {
    int col = blockIdx.x * 128 + threadIdx.x;
    int jc = blockIdx.y;
    float a = offa[jc * 1024 + col];
    float b = offb[jc * 1024 + col];
    for (int qb = 0; qb < 64; qb += 4) {
        float e[4], ebv[4], w[4];
#pragma unroll
        for (int i = 0; i < 4; i++) {
            int c = bc[jc * 64 + qb + i];
            e[i] = ew[c]; ebv[i] = eb[c];
            w[i] = __ldg(&W1[(size_t)c * Hh + col]);
        }
#pragma unroll
        for (int i = 0; i < 4; i++) {
            int j = jc * 64 + qb + i;
            float s = (e[i] > 0.f) ? 1.f : ((e[i] < 0.f) ? -1.f : 0.f);
            a += s * e[i] * w[i];
            b += s * ebv[i] * w[i];
            alpha[(size_t)(j + 1) * Hh + col] = a;
            beta[(size_t)(j + 1) * Hh + col] = b;
        }
    }
}

// ---------------- PWL eval (merged graphs, vectorized) -----------------------
__global__ void k_pwl(const float* __restrict__ fe0, const float* __restrict__ fe1,
                      const int* __restrict__ esrc, const int* __restrict__ cnt,
                      const float* __restrict__ bt,
                      const float* __restrict__ alpha, const float* __restrict__ beta,
                      __half* __restrict__ Ehp) {
    int g = blockIdx.y;
    int p = blockIdx.x;
    if (p >= cnt[g]) return;
    const float* fe = g ? fe1 : fe0;
    float f = fe[esrc[g * MAXP + p]];
    int lo = 0, hi = 1024;
    while (lo < hi) {
        int m = (lo + hi) >> 1;
        if (__ldg(&bt[m]) <= f) lo = m + 1; else hi = m;
    }
    const float4* ra = (const float4*)(alpha + (size_t)lo * Hh);
    const float4* rb = (const float4*)(beta + (size_t)lo * Hh);
    __half* E1 = Ehp + (size_t)g * 2 * ((size_t)MAXP * Hh) + (size_t)p * Hh;
    int c4 = threadIdx.x * 2;
    float4 a0 = __ldg(&ra[c4]),     a1 = __ldg(&ra[c4 + 1]);
    float4 b0 = __ldg(&rb[c4]),     b1 = __ldg(&rb[c4 + 1]);
    __half2 h0 = __floats2half2_rn(fmaf(f, a0.x, b0.x), fmaf(f, a0.y, b0.y));
    __half2 h1 = __floats2half2_rn(fmaf(f, a0.z, b0.z), fmaf(f, a0.w, b0.w));
    __half2 h2 = __floats2half2_rn(fmaf(f, a1.x, b1.x), fmaf(f, a1.y, b1.y));
    __half2 h3 = __floats2half2_rn(fmaf(f, a1.z, b1.z), fmaf(f, a1.w, b1.w));
    uint4 o;
    o.x = *(uint32_t*)&h0; o.y = *(uint32_t*)&h1;
    o.z = *(uint32_t*)&h2; o.w = *(uint32_t*)&h3;
    *(uint4*)(E1 + threadIdx.x * 8) = o;
}

// ------------------- weight transpose fp16 (merged, z=weight) ---------------
__global__ void k_wh(const float* __restrict__ W0, const float* __restrict__ W1,
                     const float* __restrict__ W2, const float* __restrict__ W3,
                     const float* __restrict__ W4, const float* __restrict__ W5,
                     const float* __restrict__ W6, const float* __restrict__ W7,
                     const float* __restrict__ W8, __half* __restrict__ Tbase) {
    const float* Ws[9] = { W0, W1, W2, W3, W4, W5, W6, W7, W8 };
    const float* W = Ws[blockIdx.z];
    __half* Th = Tbase + (size_t)blockIdx.z * Hh * Hh;
    __shared__ float tile[32][33];
    int n0 = blockIdx.x << 5, k0 = blockIdx.y << 5;
    int tx = threadIdx.x, ty = threadIdx.y;
    for (int i = 0; i < 32; i += 8)
        tile[ty + i][tx] = W[(size_t)(k0 + ty + i) * Hh + n0 + tx];
    __syncthreads();
    for (int i = 0; i < 32; i += 8)
        Th[(size_t)(n0 + ty + i) * Hh + k0 + tx] = __float2half(tile[tx][ty + i]);
}

// ---------------- affinity transpose + hi/lo split (z=which) -----------------
__global__ void k_whl(const float* __restrict__ W0, const float* __restrict__ W1,
                      __half* __restrict__ ThB, __half* __restrict__ TlB) {
    const float* W = blockIdx.z ? W1 : W0;
    __half* Th = ThB + (size_t)blockIdx.z * Hh * Hh;
    __half* Tl = TlB + (size_t)blockIdx.z * Hh * Hh;
    __shared__ float tile[32][33];
    int n0 = blockIdx.x << 5, k0 = blockIdx.y << 5;
    int tx = threadIdx.x, ty = threadIdx.y;
    for (int i = 0; i < 32; i += 8)
        tile[ty + i][tx] = W[(size_t)(k0 + ty + i) * Hh + n0 + tx];
    __syncthreads();
    for (int i = 0; i < 32; i += 8) {
        float v = tile[tx][ty + i];
        __half h = __float2half(v);
        size_t o = (size_t)(n0 + ty + i) * Hh + k0 + tx;
        Th[o] = h;
        Tl[o] = __float2half(v - __half2float(h));
    }
}
__global__ void k_fh(const float* __restrict__ X0, const float* __restrict__ X1,
                     __half* __restrict__ H, int n) {
    int g = blockIdx.y;
    const float* X = g ? X1 : X0;
    int i = blockIdx.x * 256 + threadIdx.x;
    if (i < n) H[(size_t)g * n + i] = __float2half(X[i]);
}

// ---------------- layer-0 agg (merged graphs, 2 channels/thread) -------------
__global__ void k_agg0(const float* __restrict__ fe0, const float* __restrict__ fe1,
                       const int* __restrict__ esrc, const int* __restrict__ rowptr,
                       const int* __restrict__ colj, const float* __restrict__ aval,
                       const float* __restrict__ ew, const float* __restrict__ eb,
                       const float* __restrict__ ndx, const float* __restrict__ ndsx,
                       __half* __restrict__ oh) {
    __shared__ int   scol[Nn];
    __shared__ float sf[Nn];
    __shared__ float sa[Nn];
    int g = blockIdx.x >> 9;
    int r = blockIdx.x & 511;
    const float* fe = g ? fe1 : fe0;
    int b = r >> 6;
    int c = (blockIdx.y << 9) + threadIdx.x * 2;
    const int* rp = rowptr + g * (BN + 1);
    int s = rp[r], e = rp[r + 1];
    int n = e - s;
    if (threadIdx.x < n) {
        scol[threadIdx.x] = colj[g * MAXP + s + threadIdx.x];
        sf[threadIdx.x] = fe[esrc[g * MAXP + s + threadIdx.x]];
        sa[threadIdx.x] = aval[g * MAXP + s + threadIdx.x];
    }
    __syncthreads();
    const size_t MSZ = (size_t)BN * Hh;
    float2 w = *(const float2*)(ew + c);
    float2 bb = *(const float2*)(eb + c);
    float acc0 = 0.f, acc1 = 0.f;
    for (int q = 0; q < n; q++) {
        float2 nd = *(const float2*)(ndx + g * MSZ + (size_t)((b << 6) + scol[q]) * Hh + c);
        acc0 += sa[q] * (sf[q] * w.x + bb.x) * nd.x;
        acc1 += sa[q] * (sf[q] * w.y + bb.y) * nd.y;
    }
    float2 ns = *(const float2*)(ndsx + g * MSZ + (size_t)r * Hh + c);
    float v0 = fmaxf(acc0, 0.f) + fmaxf(ns.x, 0.f);
    float v1 = fmaxf(acc1, 0.f) + fmaxf(ns.y, 0.f);
    __half2 hv = __floats2half2_rn(v0, v1);
    *(__half2*)(oh + g * MSZ + (size_t)r * Hh + c) = hv;
}

// ---------------- agg with fp16 edges (merged, 2 ch/thread, +lo split) -------
__global__ void k_aggh(const __half* __restrict__ Ebase, const int* __restrict__ rowptr,
                       const int* __restrict__ colj, const float* __restrict__ aval,
                       const float* __restrict__ ndx, const float* __restrict__ ndsx,
                       float* __restrict__ embo, __half* __restrict__ oh,
                       __half* __restrict__ ol) {
    __shared__ int   scol[Nn];
    __shared__ float sa[Nn];
    int g = blockIdx.x >> 9;
    int r = blockIdx.x & 511;
    int b = r >> 6;
    int c = (blockIdx.y << 9) + threadIdx.x * 2;
    const int* rp = rowptr + g * (BN + 1);
    int s = rp[r], e = rp[r + 1];
    int n = e - s;
    if (threadIdx.x < n) {
        scol[threadIdx.x] = colj[g * MAXP + s + threadIdx.x];
        sa[threadIdx.x] = aval[g * MAXP + s + threadIdx.x];
    }
    __syncthreads();
    const size_t MSZ = (size_t)BN * Hh;
    const __half* E = Ebase + (size_t)g * 2 * ((size_t)MAXP * Hh);
    float acc0 = 0.f, acc1 = 0.f;
    for (int q = 0; q < n; q++) {
        __half2 ev = *(const __half2*)(E + (size_t)(s + q) * Hh + c);
        float2 nd = *(const float2*)(ndx + g * MSZ + (size_t)((b << 6) + scol[q]) * Hh + c);
        acc0 += sa[q] * __low2float(ev) * nd.x;
        acc1 += sa[q] * __high2float(ev) * nd.y;
    }
    float2 ns = *(const float2*)(ndsx + g * MSZ + (size_t)r * Hh + c);
    float v0 = fmaxf(acc0, 0.f) + fmaxf(ns.x, 0.f);
    float v1 = fmaxf(acc1, 0.f) + fmaxf(ns.y, 0.f);
    size_t o = g * MSZ + (size_t)r * Hh + c;
    if (embo) *(float2*)(embo + o) = make_float2(v0, v1);
    __half2 h2v = __floats2half2_rn(v0, v1);
    if (oh) *(__half2*)(oh + o) = h2v;
    if (ol) {
        float l0 = v0 - __half2float(__low2half(h2v));
        float l1 = v1 - __half2float(__high2half(h2v));
        *(__half2*)(ol + o) = __floats2half2_rn(l0, l1);
    }
}

// ------------- batched NT GEMM K-split: Sp[z][b] = T[b]@E[b]^T (K chunk) -----
__global__ void __launch_bounds__(256)
k_bmm_nt(const float* __restrict__ T, const float* __restrict__ E, float* __restrict__ Sp) {
    int b = blockIdx.x, zk = blockIdx.y;
    const float* Tb = T + (size_t)b * Nn * Hh;
    const float* Eb = E + (size_t)b * Nn * Hh;
    __shared__ float Ts[16][68];
    __shared__ float Es[16][68];
    int t = threadIdx.x, tx = t & 15, ty = t >> 4;
    int lr = t >> 2, lk = (t & 3) << 2;
    float acc[4][4];
#pragma unroll
    for (int i = 0; i < 4; i++)
#pragma unroll
        for (int j = 0; j < 4; j++) acc[i][j] = 0.f;
    int kbeg = zk << 8;
    for (int k0 = kbeg; k0 < kbeg + 256; k0 += 16) {
        float4 a = *(const float4*)(Tb + (size_t)lr * Hh + k0 + lk);
        float4 e = *(const float4*)(Eb + (size_t)lr * Hh + k0 + lk);
        __syncthreads();
        Ts[lk + 0][lr] = a.x; Ts[lk + 1][lr] = a.y; Ts[lk + 2][lr] = a.z; Ts[lk + 3][lr] = a.w;
        Es[lk + 0][lr] = e.x; Es[lk + 1][lr] = e.y; Es[lk + 2][lr] = e.z; Es[lk + 3][lr] = e.w;
        __syncthreads();
#pragma unroll
        for (int k = 0; k < 16; k++) {
            float4 av = *(float4*)&Ts[k][ty << 2];
            float4 bv = *(float4*)&Es[k][tx << 2];
            acc[0][0] += av.x * bv.x; acc[0][1] += av.x * bv.y; acc[0][2] += av.x * bv.z; acc[0][3] += av.x * bv.w;
            acc[1][0] += av.y * bv.x; acc[1][1] += av.y * bv.y; acc[1][2] += av.y * bv.z; acc[1][3] += av.y * bv.w;
            acc[2][0] += av.z * bv.x; acc[2][1] += av.z * bv.y; acc[2][2] += av.z * bv.z; acc[2][3] += av.z * bv.w;
            acc[3][0] += av.w * bv.x; acc[3][1] += av.w * bv.y; acc[3][2] += av.w * bv.z; acc[3][3] += av.w * bv.w;
        }
    }
    float* out = Sp + ((size_t)zk * Bb + b) * (Nn * Nn);
#pragma unroll
    for (int ii = 0; ii < 4; ii++)
#pragma unroll
        for (int jj = 0; jj < 4; jj++)
            out[((ty << 2) + ii) * Nn + (tx << 2) + jj] = acc[ii][jj];
}

// ---------------- U (merged): g=0: s@emb2 ; g=1: s^T@emb1 --------------------
__global__ void k_su(const float* __restrict__ S, const float* __restrict__ Emb1,
                     const float* __restrict__ Emb2, __half* __restrict__ Uh) {
    int idx = blockIdx.x;
    int g = idx >> 9;
    int blk = idx & 511;
    int b = blk >> 6, i = blk & 63;
    const float* Emb = g ? Emb1 : Emb2;
    __shared__ float srow[Nn];
    int t = threadIdx.x;
    if (t < Nn)
        srow[t] = g ? S[b * (Nn * Nn) + t * Nn + i]
                    : S[b * (Nn * Nn) + i * Nn + t];
    __syncthreads();
    const size_t MSZ = (size_t)BN * Hh;
    for (int c = t; c < Hh; c += 256) {
        float acc = 0.f;
#pragma unroll 8
        for (int j = 0; j < Nn; j++)
            acc += srow[j] * Emb[(size_t)((b << 6) + j) * Hh + c];
        Uh[g * MSZ + (size_t)blk * Hh + c] = __float2half(acc);
    }
}

// ---------------- sinkhorn (reads sum of 4 K-split partials) -----------------
__global__ void k_sinkhorn(const float* __restrict__ Sp, float* __restrict__ out,
                           const int* __restrict__ n1, const int* __restrict__ n2,
                           const int* __restrict__ itp) {
    __shared__ float ls[64][65];
    int b = blockIdx.x, t = threadIdx.x;
    int a1 = n1[b], a2 = n2[b];
    int tb = (a1 > a2);
    int nr = tb ? a2 : a1;
    int nc = tb ? a1 : a2;
    for (int e = t; e < 4096; e += 256) {
        int r = e >> 6, c = e & 63;
        int idx = tb ? (c * 64 + r) : (r * 64 + c);
        float v = 0.f;
#pragma unroll
        for (int zz = 0; zz < 4; zz++)
            v += Sp[((size_t)zz * Bb + b) * 4096 + idx];
        ls[r][c] = (r < nr && c < nc) ? v / 0.05f : NEGV;
    }
    __syncthreads();
    int iters = *itp;
    int w = t >> 5, lane = t & 31;
    for (int it = 0; it < iters; it++) {
        if ((it & 1) == 0) {
            for (int r = w; r < 64; r += 8) {
                float x0 = ls[r][lane], x1 = ls[r][lane + 32];
                float m = fmaxf(x0, x1);
                for (int o = 16; o; o >>= 1) m = fmaxf(m, __shfl_xor_sync(0xffffffffu, m, o));
                float sm = expf(x0 - m) + expf(x1 - m);
                for (int o = 16; o; o >>= 1) sm += __shfl_xor_sync(0xffffffffu, sm, o);
                float lse = m + logf(sm);
                bool rm = (r < nr);
                ls[r][lane]      = (rm && lane < nc)        ? x0 - lse : NEGV;
                ls[r][lane + 32] = (rm && (lane + 32) < nc) ? x1 - lse : NEGV;
            }
        } else {
            for (int c = w; c < 64; c += 8) {
                float x0 = ls[lane][c], x1 = ls[lane + 32][c];
                float m = fmaxf(x0, x1);
                for (int o = 16; o; o >>= 1) m = fmaxf(m, __shfl_xor_sync(0xffffffffu, m, o));
                float sm = expf(x0 - m) + expf(x1 - m);
                for (int o = 16; o; o >>= 1) sm += __shfl_xor_sync(0xffffffffu, sm, o);
                float lse = m + logf(sm);
                bool cm = (c < nc);
                ls[lane][c]      = (cm && lane < nr)        ? x0 - lse : NEGV;
                ls[lane + 32][c] = (cm && (lane + 32) < nr) ? x1 - lse : NEGV;
            }
        }
        __syncthreads();
    }
    for (int e = t; e < 4096; e += 256) {
        int r = e >> 6, c = e & 63;
        float v = (r < nr && c < nc) ? expf(ls[r][c]) : 0.f;
        if (tb) out[b * 4096 + c * 64 + r] = v;
        else    out[b * 4096 + r * 64 + c] = v;
    }
}

// ------------------------------- launch --------------------------------------
extern "C" void kernel_launch(void* const* d_in, const int* in_sizes, int n_in,
                              void* d_out, int out_size) {
    (void)in_sizes; (void)n_in; (void)out_size;
    const float* fn[2]   = { (const float*)d_in[0], (const float*)d_in[1] };
    const float* Aadj[2] = { (const float*)d_in[2], (const float*)d_in[3] };
    const float* fe[2]   = { (const float*)d_in[4], (const float*)d_in[5] };
    const float* lw[3][6];
    for (int l = 0; l < 3; l++)
        for (int k = 0; k < 6; k++)
            lw[l][k] = (const float*)d_in[6 + l * 6 + k];
    const float* aff1 = (const float*)d_in[24];
    const float* aff2 = (const float*)d_in[25];
    const float* cw   = (const float*)d_in[26];
    const float* cb   = (const float*)d_in[27];
    const int*   n1   = (const int*)d_in[28];
    const int*   n2   = (const int*)d_in[29];
    const int*   itp  = (const int*)d_in[30];
    float* out = (float*)d_out;

    void* p;
    cudaGetSymbolAddress(&p, g_Ehp);    __half* Ehp   = (__half*)p;
    cudaGetSymbolAddress(&p, g_emb32);  float*  emb32 = (float*)p;
    cudaGetSymbolAddress(&p, g_embh);   __half* ebh   = (__half*)p;
    cudaGetSymbolAddress(&p, g_embl);   __half* ebl   = (__half*)p;
    cudaGetSymbolAddress(&p, g_ndx);    float*  ndx   = (float*)p;
    cudaGetSymbolAddress(&p, g_ndsx);   float*  ndsx  = (float*)p;
    cudaGetSymbolAddress(&p, g_t);      float*  tbuf  = (float*)p;
    cudaGetSymbolAddress(&p, g_uh);     __half* uh    = (__half*)p;
    cudaGetSymbolAddress(&p, g_fnh);    __half* fnh   = (__half*)p;
    cudaGetSymbolAddress(&p, g_wth);    __half* wth   = (__half*)p;
    cudaGetSymbolAddress(&p, g_afh);    __half* afh   = (__half*)p;
    cudaGetSymbolAddress(&p, g_afl);    __half* afl   = (__half*)p;
    cudaGetSymbolAddress(&p, g_alpha);  float*  alpha = (float*)p;
    cudaGetSymbolAddress(&p, g_beta);   float*  beta  = (float*)p;
    cudaGetSymbolAddress(&p, g_bt);     float*  bt    = (float*)p;
    cudaGetSymbolAddress(&p, g_bc);     int*    bc    = (int*)p;
    cudaGetSymbolAddress(&p, g_b0a);    float*  b0a   = (float*)p;
    cudaGetSymbolAddress(&p, g_b0b);    float*  b0b   = (float*)p;
    cudaGetSymbolAddress(&p, g_da);     float*  da    = (float*)p;
    cudaGetSymbolAddress(&p, g_db);     float*  db    = (float*)p;
    cudaGetSymbolAddress(&p, g_offa);   float*  offa  = (float*)p;
    cudaGetSymbolAddress(&p, g_offb);   float*  offb  = (float*)p;
    cudaGetSymbolAddress(&p, g_spart);  float*  spart = (float*)p;
    cudaGetSymbolAddress(&p, g_ssk);    float*  ssk   = (float*)p;
    cudaGetSymbolAddress(&p, g_rowcnt); int* rowcnt   = (int*)p;
    cudaGetSymbolAddress(&p, g_rowptr); int* rowptr   = (int*)p;
    cudaGetSymbolAddress(&p, g_colj);   int* colj     = (int*)p;
    cudaGetSymbolAddress(&p, g_esrc);   int* esrc     = (int*)p;
    cudaGetSymbolAddress(&p, g_aval);   float* aval   = (float*)p;
    cudaGetSymbolAddress(&p, g_cnt);    int* cnt      = (int*)p;

    const size_t ESZ = (size_t)MAXP * Hh;
    const size_t MSZ = (size_t)BN * Hh;
    const size_t WSZ = (size_t)Hh * Hh;
#define E1P(g)     (Ehp + ((size_t)(g) * 2 + 0) * ESZ)
#define M32(g)     (emb32 + (size_t)(g) * MSZ)
#define EBH(pp, g) (ebh + ((size_t)(pp) * 2 + (g)) * MSZ)
#define WH(i)      (wth + (size_t)(i) * WSZ)

    cudaStream_t s0 = 0;
    cudaStream_t s2 = g_si.s2;

    // ---- fork ----
    cudaEventRecord(g_si.evRoot, s0);
    cudaStreamWaitEvent(s2, g_si.evRoot, 0);

    // ---- side stream: affinity splits + PWL table build ----
    k_whl<<<dim3(32, 32, 2), dim3(32, 8), 0, s2>>>(aff1, aff2, afh, afl);
    cudaEventRecord(g_si.evE, s2);              // aff splits ready
    k_sort<<<1, 1024, 0, s2>>>(lw[0][4], lw[0][5], bt, bc);
    k_bd<<<dim3(8, 16, 2), 128, 0, s2>>>(lw[0][4], lw[0][5], lw[1][4], lw[1][5], bc,
                                         b0a, b0b, da, db);
    k_offs<<<8, 128, 0, s2>>>(b0a, b0b, da, db, offa, offb, alpha, beta);
    k_fillscan<<<dim3(8, 16), 128, 0, s2>>>(lw[0][4], lw[0][5], lw[1][4], bc,
                                            offa, offb, alpha, beta);

    // ---- main stream: weights + compaction FIRST (evA early), features after -
    k_wh<<<dim3(32, 32, 9), dim3(32, 8), 0, s0>>>(lw[0][0], lw[0][2], lw[1][0], lw[1][2],
                                                  lw[2][0], lw[2][2], lw[2][4], cw,
                                                  cw + WSZ, wth);
    cudaEventRecord(g_si.evW, s0);              // weights ready (for E2 GEMM on s2)
    k_count<<<dim3(8, 2), 64, 0, s0>>>(Aadj[0], Aadj[1], rowcnt);
    k_scan<<<2, BN, 0, s0>>>(rowcnt, rowptr, cnt);
    k_fill<<<dim3(8, 2), 64, 0, s0>>>(Aadj[0], Aadj[1], rowptr, colj, esrc, aval);
    cudaEventRecord(g_si.evA, s0);              // compaction ready (earlier now)
    k_fh<<<dim3((int)(MSZ / 256), 2), 256, 0, s0>>>(fn[0], fn[1], fnh, (int)MSZ);

    // ---- side stream: E1 eval + E2 GEMM (fp16-acc, proven safe) ----
    cudaStreamWaitEvent(s2, g_si.evA, 0);
    k_pwl<<<dim3(MAXP, 2), 128, 0, s2>>>(fe[0], fe[1], esrc, cnt, bt, alpha, beta, Ehp);
    cudaEventRecord(g_si.evB, s2);              // E1 ready
    cudaStreamWaitEvent(s2, g_si.evW, 0);
    k_h16<<<dim3(256, 8, 2), 256, 0, s2>>>(E1P(0), E1P(1), WH(6), lw[2][5],
                                           Ehp + ESZ, Ehp + 3 * ESZ, cnt);
    cudaEventRecord(g_si.evD, s2);              // E2 ready

    // ---- main stream: node layers 0-1 (fp32 acc — measured faster) ----
    k_hgemm<<<dim3(8, 8, 2), 256, 0, s0>>>(fnh, nullptr, nullptr, nullptr,
                                           WH(0), WH(1), nullptr, nullptr,
                                           lw[0][1], lw[0][3], ndx, ndsx,
                                           nullptr, nullptr, 0, 0, 0, 2 * BN, nullptr);
    k_agg0<<<dim3(1024, 2), 256, 0, s0>>>(fe[0], fe[1], esrc, rowptr, colj, aval,
                                          lw[0][4], lw[0][5], ndx, ndsx, EBH(0, 0));
    k_hgemm<<<dim3(8, 8, 2), 256, 0, s0>>>(EBH(0, 0), nullptr, nullptr, nullptr,
                                           WH(2), WH(3), nullptr, nullptr,
                                           lw[1][1], lw[1][3], ndx, ndsx,
                                           nullptr, nullptr, 0, 0, 0, 2 * BN, nullptr);
    cudaStreamWaitEvent(s0, g_si.evB, 0);
    k_aggh<<<dim3(1024, 2), 256, 0, s0>>>(E1P(0), rowptr, colj, aval, ndx, ndsx,
                                          M32(0), EBH(1, 0), ebl);
    // ---- cross-attention mid-section (overlaps E2 GEMM on s2) ----
    cudaStreamWaitEvent(s0, g_si.evE, 0);       // need aff splits
    k_hgemm<<<dim3(4, 8, 1), 256, 0, s0>>>(EBH(1, 0), nullptr, EBH(1, 0), ebl,
                                           afh, nullptr, afl, afh,
                                           nullptr, nullptr, tbuf, nullptr,
                                           nullptr, nullptr, 0, 0, 0, BN, nullptr);
    k_bmm_nt<<<dim3(8, 4), 256, 0, s0>>>(tbuf, M32(1), spart);
    k_sinkhorn<<<8, 256, 0, s0>>>(spart, ssk, n1, n2, itp);
    k_su<<<1024, 256, 0, s0>>>(ssk, M32(0), M32(1), uh);
    k_hgemm<<<dim3(8, 8, 1), 256, 0, s0>>>(EBH(1, 0), nullptr, uh, nullptr,
                                           WH(7), nullptr, WH(8), nullptr,
                                           cb, nullptr, nullptr, nullptr,
                                           EBH(0, 0), nullptr, 0, 0, 0, 2 * BN, nullptr);
    k_hgemm<<<dim3(8, 8, 2), 256, 0, s0>>>(EBH(0, 0), nullptr, nullptr, nullptr,
                                           WH(4), WH(5), nullptr, nullptr,
                                           lw[2][1], lw[2][3], ndx, ndsx,
                                           nullptr, nullptr, 0, 0, 0, 2 * BN, nullptr);
    // ---- join: layer-2 agg needs E2; M32 write REQUIRED (final bmm reads it) -
    cudaStreamWaitEvent(s0, g_si.evD, 0);
    k_aggh<<<dim3(1024, 2), 256, 0, s0>>>(Ehp + ESZ, rowptr, colj, aval, ndx, ndsx,
                                          M32(0), EBH(1, 0), ebl);
    // ---- final affinity + sinkhorn ----
    k_hgemm<<<dim3(4, 8, 1), 256, 0, s0>>>(EBH(1, 0), nullptr, EBH(1, 0), ebl,
                                           afh + WSZ, nullptr, afl + WSZ, afh + WSZ,
                                           nullptr, nullptr, tbuf, nullptr,
                                           nullptr, nullptr, 0, 0, 0, BN, nullptr);
    k_bmm_nt<<<dim3(8, 4), 256, 0, s0>>>(tbuf, M32(1), spart);
    k_sinkhorn<<<8, 256, 0, s0>>>(spart, out, n1, n2, itp);
#undef E1P
#undef M32
#undef EBH
#undef WH
}

// round 17
// speedup vs baseline: 1.1744x; 1.0389x over previous
#include <cuda_runtime.h>
#include <cuda_fp16.h>
#include <math.h>
#include <stdint.h>

#define Bb   8
#define Nn   64
#define Hh   1024
#define BN   512
#define MAXP 32768
#define NEGV -1e30f

// ------------------------------- scratch ------------------------------------
__device__ __half g_Ehp[2][2][(size_t)MAXP * Hh];   // [graph][{E1pre, E2pre}] fp16
__device__ float  g_emb32[2][(size_t)BN * Hh];
__device__ __half g_embh[4][(size_t)BN * Hh];       // [pp*2+g]
__device__ __half g_embl[2][(size_t)BN * Hh];       // lo split of current emb
__device__ float  g_ndx[2][(size_t)BN * Hh];
__device__ float  g_ndsx[2][(size_t)BN * Hh];
__device__ float  g_t[(size_t)BN * Hh];
__device__ __half g_uh[2][(size_t)BN * Hh];
__device__ __half g_fnh[2][(size_t)BN * Hh];
__device__ __half g_wth[9][(size_t)Hh * Hh];
__device__ __half g_afh[2][(size_t)Hh * Hh];        // aff^T hi
__device__ __half g_afl[2][(size_t)Hh * Hh];        // aff^T lo
__device__ float  g_alpha[(size_t)1025 * Hh];
__device__ float  g_beta[(size_t)1025 * Hh];
__device__ float  g_bt[1024];
__device__ int    g_bc[1024];
__device__ float  g_b0a[16 * 1024], g_b0b[16 * 1024];
__device__ float  g_da[16 * 1024],  g_db[16 * 1024];
__device__ float  g_offa[16 * 1024], g_offb[16 * 1024];
__device__ float  g_spart[4 * Bb * Nn * Nn];
__device__ float  g_ssk[Bb * Nn * Nn];
__device__ int    g_rowcnt[2][BN];
__device__ int    g_rowptr[2][BN + 1];
__device__ int    g_colj[2][MAXP];
__device__ int    g_esrc[2][MAXP];
__device__ float  g_aval[2][MAXP];
__device__ int    g_cnt[2];

// ---- streams/events created at static-init ----------------------------------
struct GInit {
    cudaStream_t s2, s3;
    cudaEvent_t evRoot, evA, evW, evB, evD, evE;
    GInit() {
        cudaStreamCreateWithFlags(&s2, cudaStreamNonBlocking);
        cudaStreamCreateWithFlags(&s3, cudaStreamNonBlocking);
        cudaEventCreateWithFlags(&evRoot, cudaEventDisableTiming);
        cudaEventCreateWithFlags(&evA, cudaEventDisableTiming);
        cudaEventCreateWithFlags(&evW, cudaEventDisableTiming);
        cudaEventCreateWithFlags(&evB, cudaEventDisableTiming);
        cudaEventCreateWithFlags(&evD, cudaEventDisableTiming);
        cudaEventCreateWithFlags(&evE, cudaEventDisableTiming);
    }
};
static GInit g_si;

// ------------------------------- helpers ------------------------------------
__device__ __forceinline__ uint32_t smem_u32(const void* p) {
    uint32_t a;
    asm("{ .reg .u64 t; cvta.to.shared.u64 t, %1; cvt.u32.u64 %0, t; }" : "=r"(a) : "l"(p));
    return a;
}
#define MMA16816(d, a, b) \
    asm volatile("mma.sync.aligned.m16n8k16.row.col.f32.f16.f16.f32 " \
        "{%0,%1,%2,%3}, {%4,%5,%6,%7}, {%8,%9}, {%0,%1,%2,%3};" \
        : "+f"((d)[0]), "+f"((d)[1]), "+f"((d)[2]), "+f"((d)[3]) \
        : "r"((a)[0]), "r"((a)[1]), "r"((a)[2]), "r"((a)[3]), \
          "r"((b)[0]), "r"((b)[1]))
#define MMA16816H(d, a, b) \
    asm volatile("mma.sync.aligned.m16n8k16.row.col.f16.f16.f16.f16 " \
        "{%0,%1}, {%2,%3,%4,%5}, {%6,%7}, {%0,%1};" \
        : "+r"((d)[0]), "+r"((d)[1]) \
        : "r"((a)[0]), "r"((a)[1]), "r"((a)[2]), "r"((a)[3]), \
          "r"((b)[0]), "r"((b)[1]))
#define LDSM4(r0, r1, r2, r3, addr) \
    asm volatile("ldmatrix.sync.aligned.m8n8.x4.shared.b16 {%0,%1,%2,%3}, [%4];" \
        : "=r"(r0), "=r"(r1), "=r"(r2), "=r"(r3) : "r"(addr))
#define CPA16(dst, src, nbytes) \
    asm volatile("cp.async.ca.shared.global [%0], [%1], 16, %2;" \
        :: "r"(dst), "l"(src), "r"(nbytes))
#define CPA_COMMIT() asm volatile("cp.async.commit_group;")
#define CPA_WAIT0()  asm volatile("cp.async.wait_group 0;")

// ---------------- fp32-accumulate GEMM (node/cross/affinity) -----------------
__global__ void __launch_bounds__(256, 2)
k_hgemm(const __half* __restrict__ A0, const __half* __restrict__ A1g,
        const __half* __restrict__ A2, const __half* __restrict__ A3,
        const __half* __restrict__ B0, const __half* __restrict__ B1,
        const __half* __restrict__ B2, const __half* __restrict__ B3,
        const float* __restrict__ bias0, const float* __restrict__ bias1,
        float* __restrict__ C0, float* __restrict__ C1z,
        __half* __restrict__ Oh0, __half* __restrict__ Oh1g,
        int relu_a, int relu_oh, int zmode,
        int M, const int* __restrict__ Mptr)
{
    int z = blockIdx.z;
    const __half* A = A0;
    const __half* Bsel = B0;
    const float* bias = bias0;
    float* C = C0;
    __half* Oh = Oh0;
    if (zmode == 0) {
        if (Mptr) M = *Mptr;
        if (z == 1) { Bsel = B1; bias = bias1; C = C1z; Oh = nullptr; }
    } else {
        M = Mptr[z];
        if (z == 1) { A = A1g; Oh = Oh1g; C = C1z; }
    }
    int m0 = blockIdx.x << 7;
    if (m0 >= M) return;
    int n0 = blockIdx.y << 7;

    __shared__ __align__(16) char smraw[40960];
    uint32_t sb = smem_u32(smraw);
    const uint32_t STG = 2 * 128 * 40 * 2;
    const uint32_t OPS = 128 * 40 * 2;

    int t = threadIdx.x, lane = t & 31, wid = t >> 5;
    int wm = wid & 3, wn = wid >> 2;

    int lrow = t >> 1;
    int lhalf = (t & 1) << 4;
    size_t aoff = (size_t)(m0 + lrow) * Hh + lhalf;
    size_t boff = (size_t)(n0 + lrow) * Hh + lhalf;
    int abytes = (m0 + lrow < M) ? 16 : 0;
    uint32_t ldst = (uint32_t)(lrow * 40 + lhalf) * 2;

    float acc[2][8][4];
#pragma unroll
    for (int i = 0; i < 2; i++)
#pragma unroll
        for (int j = 0; j < 8; j++)
#pragma unroll
            for (int k = 0; k < 4; k++) acc[i][j][k] = 0.f;

    const __half* PA[3] = { A, A2, A3 };
    const __half* PB[3] = { Bsel, B2, B3 };
    int npairs = A3 ? 3 : (A2 ? 2 : 1);
    int T = npairs << 5;

    auto prefetch = [&](int it, int stg) {
        int pr = it >> 5;
        const __half* pA = PA[pr] + aoff + ((it & 31) << 5);
        const __half* pB = PB[pr] + boff + ((it & 31) << 5);
        uint32_t dA = sb + (uint32_t)stg * STG + ldst;
        CPA16(dA, pA, abytes);
        CPA16(dA + 16, pA + 8, abytes);
        uint32_t dB = dA + OPS;
        CPA16(dB, pB, 16);
        CPA16(dB + 16, pB + 8, 16);
        CPA_COMMIT();
    };

    prefetch(0, 0);
    int fr = lane & 15;
    int fk = (lane >> 4) << 3;
    const __half2 z2 = __float2half2_rn(0.f);

    for (int it = 0; it < T; it++) {
        CPA_WAIT0();
        __syncthreads();
        if (it + 1 < T) prefetch(it + 1, (it + 1) & 1);
        uint32_t stage = sb + (uint32_t)(it & 1) * STG;
#pragma unroll
        for (int ks = 0; ks < 2; ks++) {
            int kc = ks << 4;
            uint32_t af[2][4];
#pragma unroll
            for (int mt = 0; mt < 2; mt++) {
                uint32_t addr = stage + (uint32_t)((wm * 32 + mt * 16 + fr) * 40 + kc + fk) * 2;
                LDSM4(af[mt][0], af[mt][1], af[mt][2], af[mt][3], addr);
                if (relu_a) {
#pragma unroll
                    for (int q = 0; q < 4; q++) {
                        __half2 h = *(__half2*)&af[mt][q];
                        h = __hmax2(h, z2);
                        af[mt][q] = *(uint32_t*)&h;
                    }
                }
            }
            uint32_t bf[8][2];
#pragma unroll
            for (int nq = 0; nq < 4; nq++) {
                uint32_t r0, r1, r2, r3;
                uint32_t addr = stage + OPS +
                    (uint32_t)((wn * 64 + nq * 16 + fr) * 40 + kc + fk) * 2;
                LDSM4(r0, r1, r2, r3, addr);
                bf[nq * 2][0] = r0; bf[nq * 2][1] = r2;
                bf[nq * 2 + 1][0] = r1; bf[nq * 2 + 1][1] = r3;
            }
#pragma unroll
            for (int mt = 0; mt < 2; mt++)
#pragma unroll
                for (int nt = 0; nt < 8; nt++)
                    MMA16816(acc[mt][nt], af[mt], bf[nt]);
        }
    }

    float* ssm = (float*)smraw;
#pragma unroll
    for (int half = 0; half < 2; half++) {
        __syncthreads();
        if (wn == half) {
#pragma unroll
            for (int mt = 0; mt < 2; mt++)
#pragma unroll
                for (int nt = 0; nt < 8; nt++) {
                    int r = wm * 32 + mt * 16 + (lane >> 2);
                    int cl = nt * 8 + ((lane & 3) << 1);
                    ssm[r * 68 + cl]           = acc[mt][nt][0];
                    ssm[r * 68 + cl + 1]       = acc[mt][nt][1];
                    ssm[(r + 8) * 68 + cl]     = acc[mt][nt][2];
                    ssm[(r + 8) * 68 + cl + 1] = acc[mt][nt][3];
                }
        }
        __syncthreads();
        int r = t >> 1, cl = (t & 1) << 5;
        if (m0 + r < M) {
            int gc = n0 + half * 64 + cl;
            size_t gb = (size_t)(m0 + r) * Hh + gc;
#pragma unroll
            for (int i = 0; i < 8; i++) {
                float4 v = *(float4*)&ssm[r * 68 + cl + i * 4];
                if (bias) {
                    float4 bv = *(const float4*)(bias + gc + i * 4);
                    v.x += bv.x; v.y += bv.y; v.z += bv.z; v.w += bv.w;
                }
                if (C) *(float4*)&C[gb + i * 4] = v;
                if (Oh) {
                    float v0 = v.x, v1 = v.y, v2 = v.z, v3 = v.w;
                    if (relu_oh) {
                        v0 = fmaxf(v0, 0.f); v1 = fmaxf(v1, 0.f);
                        v2 = fmaxf(v2, 0.f); v3 = fmaxf(v3, 0.f);
                    }
                    __half2 h01 = __floats2half2_rn(v0, v1);
                    __half2 h23 = __floats2half2_rn(v2, v3);
                    *(uint2*)&Oh[gb + i * 4] =
                        make_uint2(*(uint32_t*)&h01, *(uint32_t*)&h23);
                }
            }
        }
    }
}

// ---------------- fp16-accumulate GEMM (edge E2 ONLY — proven safe + faster) -
__global__ void __launch_bounds__(256, 2)
k_h16(const __half* __restrict__ A0, const __half* __restrict__ A1g,
      const __half* __restrict__ B0, const float* __restrict__ bias,
      __half* __restrict__ Oh0, __half* __restrict__ Oh1g,
      const int* __restrict__ Mptr)
{
    int z = blockIdx.z;
    const __half* A = z ? A1g : A0;
    __half* Oh = z ? Oh1g : Oh0;
    int M = Mptr[z];
    int m0 = blockIdx.x << 7;
    if (m0 >= M) return;
    int n0 = blockIdx.y << 7;

    __shared__ __align__(16) char smraw[40960];
    uint32_t sb = smem_u32(smraw);
    const uint32_t STG = 2 * 128 * 40 * 2;
    const uint32_t OPS = 128 * 40 * 2;

    int t = threadIdx.x, lane = t & 31, wid = t >> 5;
    int wm = wid & 3, wn = wid >> 2;

    int lrow = t >> 1;
    int lhalf = (t & 1) << 4;
    size_t aoff = (size_t)(m0 + lrow) * Hh + lhalf;
    size_t boff = (size_t)(n0 + lrow) * Hh + lhalf;
    int abytes = (m0 + lrow < M) ? 16 : 0;
    uint32_t ldst = (uint32_t)(lrow * 40 + lhalf) * 2;

    uint32_t acc[2][8][2];
#pragma unroll
    for (int i = 0; i < 2; i++)
#pragma unroll
        for (int j = 0; j < 8; j++) { acc[i][j][0] = 0u; acc[i][j][1] = 0u; }

    auto prefetch = [&](int it, int stg) {
        int ko = it << 5;
        const __half* pA = A + aoff + ko;
        const __half* pB = B0 + boff + ko;
        uint32_t dA = sb + (uint32_t)stg * STG + ldst;
        CPA16(dA, pA, abytes);
        CPA16(dA + 16, pA + 8, abytes);
        uint32_t dB = dA + OPS;
        CPA16(dB, pB, 16);
        CPA16(dB + 16, pB + 8, 16);
        CPA_COMMIT();
    };

    prefetch(0, 0);
    int fr = lane & 15;
    int fk = (lane >> 4) << 3;
    const __half2 z2 = __float2half2_rn(0.f);

    for (int it = 0; it < 32; it++) {
        CPA_WAIT0();
        __syncthreads();
        if (it + 1 < 32) prefetch(it + 1, (it + 1) & 1);
        uint32_t stage = sb + (uint32_t)(it & 1) * STG;
#pragma unroll
        for (int ks = 0; ks < 2; ks++) {
            int kc = ks << 4;
            uint32_t af[2][4];
#pragma unroll
            for (int mt = 0; mt < 2; mt++) {
                uint32_t addr = stage + (uint32_t)((wm * 32 + mt * 16 + fr) * 40 + kc + fk) * 2;
                LDSM4(af[mt][0], af[mt][1], af[mt][2], af[mt][3], addr);
#pragma unroll
                for (int q = 0; q < 4; q++) {
                    __half2 h = *(__half2*)&af[mt][q];
                    h = __hmax2(h, z2);
                    af[mt][q] = *(uint32_t*)&h;
                }
            }
            uint32_t bf[8][2];
#pragma unroll
            for (int nq = 0; nq < 4; nq++) {
                uint32_t r0, r1, r2, r3;
                uint32_t addr = stage + OPS +
                    (uint32_t)((wn * 64 + nq * 16 + fr) * 40 + kc + fk) * 2;
                LDSM4(r0, r1, r2, r3, addr);
                bf[nq * 2][0] = r0; bf[nq * 2][1] = r2;
                bf[nq * 2 + 1][0] = r1; bf[nq * 2 + 1][1] = r3;
            }
#pragma unroll
            for (int mt = 0; mt < 2; mt++)
#pragma unroll
                for (int nt = 0; nt < 8; nt++)
                    MMA16816H(acc[mt][nt], af[mt], bf[nt]);
        }
    }

    float* ssm = (float*)smraw;
#pragma unroll
    for (int half = 0; half < 2; half++) {
        __syncthreads();
        if (wn == half) {
#pragma unroll
            for (int mt = 0; mt < 2; mt++)
#pragma unroll
                for (int nt = 0; nt < 8; nt++) {
                    int r = wm * 32 + mt * 16 + (lane >> 2);
                    int cl = nt * 8 + ((lane & 3) << 1);
                    __half2 p0 = *(__half2*)&acc[mt][nt][0];
                    __half2 p1 = *(__half2*)&acc[mt][nt][1];
                    ssm[r * 68 + cl]           = __low2float(p0);
                    ssm[r * 68 + cl + 1]       = __high2float(p0);
                    ssm[(r + 8) * 68 + cl]     = __low2float(p1);
                    ssm[(r + 8) * 68 + cl + 1] = __high2float(p1);
                }
        }
        __syncthreads();
        int r = t >> 1, cl = (t & 1) << 5;
        if (m0 + r < M) {
            int gc = n0 + half * 64 + cl;
            size_t gb = (size_t)(m0 + r) * Hh + gc;
#pragma unroll
            for (int i = 0; i < 8; i++) {
                float4 v = *(float4*)&ssm[r * 68 + cl + i * 4];
                float4 bv = *(const float4*)(bias + gc + i * 4);
                v.x += bv.x; v.y += bv.y; v.z += bv.z; v.w += bv.w;
                __half2 h01 = __floats2half2_rn(v.x, v.y);
                __half2 h23 = __floats2half2_rn(v.z, v.w);
                *(uint2*)&Oh[gb + i * 4] =
                    make_uint2(*(uint32_t*)&h01, *(uint32_t*)&h23);
            }
        }
    }
}

// ------------------------- compaction (merged graphs) -----------------------
__global__ void k_count(const float* __restrict__ A0, const float* __restrict__ A1,
                        int* __restrict__ rowcnt) {
    int g = blockIdx.y;
    const float* A = g ? A1 : A0;
    int r = blockIdx.x * 64 + threadIdx.x;
    const float* row = A + (size_t)r * Nn;
    int c = 0;
    for (int j = 0; j < Nn; j++) c += (row[j] != 0.0f);
    rowcnt[g * BN + r] = c;
}
__global__ void k_scan(const int* __restrict__ rowcnt, int* __restrict__ rowptr,
                       int* __restrict__ cnt) {
    __shared__ int sm[BN];
    int g = blockIdx.x, t = threadIdx.x;
    sm[t] = rowcnt[g * BN + t];
    __syncthreads();
    for (int off = 1; off < BN; off <<= 1) {
        int v = (t >= off) ? sm[t - off] : 0;
        __syncthreads();
        sm[t] += v;
        __syncthreads();
    }
    rowptr[g * (BN + 1) + t + 1] = sm[t];
    if (t == 0)      rowptr[g * (BN + 1)] = 0;
    if (t == BN - 1) cnt[g] = sm[BN - 1];
}
__global__ void k_fill(const float* __restrict__ A0, const float* __restrict__ A1,
                       const int* __restrict__ rowptr,
                       int* __restrict__ colj, int* __restrict__ esrc,
                       float* __restrict__ aval) {
    int g = blockIdx.y;
    const float* A = g ? A1 : A0;
    int r = blockIdx.x * 64 + threadIdx.x;
    const float* row = A + (size_t)r * Nn;
    int pos = rowptr[g * (BN + 1) + r];
    for (int j = 0; j < Nn; j++) {
        float a = row[j];
        if (a != 0.0f) {
            colj[g * MAXP + pos] = j;
            esrc[g * MAXP + pos] = r * Nn + j;
            aval[g * MAXP + pos] = a;
            pos++;
        }
    }
}

// ---------------- PWL: sort breakpoints (bitonic, 1 block) ------------------
__global__ void k_sort(const float* __restrict__ ew, const float* __restrict__ eb,
                       float* __restrict__ bt, int* __restrict__ bc) {
    __shared__ float sk[1024];
    __shared__ int   sc[1024];
    int t = threadIdx.x;
    float e = ew[t];
    sk[t] = (e != 0.f) ? (-eb[t] / e) : 3.4e38f;
    sc[t] = t;
    __syncthreads();
    for (int k = 2; k <= 1024; k <<= 1) {
        for (int j = k >> 1; j > 0; j >>= 1) {
            int ixj = t ^ j;
            if (ixj > t) {
                float a = sk[t], b = sk[ixj];
                int ca = sc[t], cb = sc[ixj];
                bool gt = (a > b) || (a == b && ca > cb);
                bool up = ((t & k) == 0);
                if (gt == up) { sk[t] = b; sk[ixj] = a; sc[t] = cb; sc[ixj] = ca; }
            }
            __syncthreads();
        }
    }
    bt[t] = sk[t];
    bc[t] = sc[t];
}

// ---------------- PWL: base partials + delta sums (merged, MLP=4) -----------
__global__ void k_bd(const float* __restrict__ ew, const float* __restrict__ eb,
                     const float* __restrict__ W1, const float* __restrict__ b1,
                     const int* __restrict__ bc,
                     float* __restrict__ b0a, float* __restrict__ b0b,
                     float* __restrict__ da, float* __restrict__ db) {
    int col = blockIdx.x * 128 + threadIdx.x;
    int ch = blockIdx.y;
    if (blockIdx.z == 0) {
        float a = 0.f, b = (ch == 0) ? b1[col] : 0.f;
        for (int qb = 0; qb < 64; qb += 4) {
            float e[4], ebv[4], w[4];
#pragma unroll
            for (int i = 0; i < 4; i++) {
                int c = ch * 64 + qb + i;
                e[i] = ew[c]; ebv[i] = eb[c];
                w[i] = __ldg(&W1[(size_t)c * Hh + col]);
            }
#pragma unroll
            for (int i = 0; i < 4; i++) {
                if (e[i] < 0.f) { a += e[i] * w[i]; b += ebv[i] * w[i]; }
                else if (e[i] == 0.f && ebv[i] > 0.f) b += ebv[i] * w[i];
            }
        }
        b0a[ch * 1024 + col] = a;
        b0b[ch * 1024 + col] = b;
    } else {
        float a = 0.f, b = 0.f;
        for (int qb = 0; qb < 64; qb += 4) {
            float e[4], ebv[4], w[4];
#pragma unroll
            for (int i = 0; i < 4; i++) {
                int c = bc[ch * 64 + qb + i];
                e[i] = ew[c]; ebv[i] = eb[c];
                w[i] = __ldg(&W1[(size_t)c * Hh + col]);
            }
#pragma unroll
            for (int i = 0; i < 4; i++) {
                float s = (e[i] > 0.f) ? 1.f : ((e[i] < 0.f) ? -1.f : 0.f);
                a += s * e[i] * w[i];
                b += s * ebv[i] * w[i];
            }
        }
        da[ch * 1024 + col] = a;
        db[ch * 1024 + col] = b;
    }
}

// ---------------- PWL: chunk offsets + segment-0 row -------------------------
__global__ void k_offs(const float* __restrict__ b0a, const float* __restrict__ b0b,
                       const float* __restrict__ da, const float* __restrict__ db,
                       float* __restrict__ offa, float* __restrict__ offb,
                       float* __restrict__ alpha, float* __restrict__ beta) {
    int col = blockIdx.x * 128 + threadIdx.x;
    float a = 0.f, b = 0.f;
#pragma unroll
    for (int cc = 0; cc < 16; cc++) { a += b0a[cc * 1024 + col]; b += b0b[cc * 1024 + col]; }
    alpha[col] = a;
    beta[col] = b;
#pragma unroll
    for (int jc = 0; jc < 16; jc++) {
        offa[jc * 1024 + col] = a;
        offb[jc * 1024 + col] = b;
        a += da[jc * 1024 + col];
        b += db[jc * 1024 + col];
    }
}

// ---------------- PWL: fill rows 1..1024 (prefetch 4) ------------------------
__global__ void k_fillscan(const float* __restrict__ ew, const float* __restrict__ eb,
                           const float* __restrict__ W1, const int* __restrict__ bc,
                           const float* __restrict__ offa, const float* __restrict__ offb,
                           float* __restrict__ alpha, float* __restrict__ beta) {
    int col = blockIdx.x * 128 + threadIdx.x;
    int jc = blockIdx.y;
    float a = offa[jc * 1024 + col];
    float b = offb[jc * 1024 + col];
    for (int qb = 0; qb < 64; qb += 4) {
        float e[4], ebv[4], w[4];
#pragma unroll
        for (int i = 0; i < 4; i++) {
            int c = bc[jc * 64 + qb + i];
            e[i] = ew[c]; ebv[i] = eb[c];
            w[i] = __ldg(&W1[(size_t)c * Hh + col]);
        }
#pragma unroll
        for (int i = 0; i < 4; i++) {
            int j = jc * 64 + qb + i;
            float s = (e[i] > 0.f) ? 1.f : ((e[i] < 0.f) ? -1.f : 0.f);
            a += s * e[i] * w[i];
            b += s * ebv[i] * w[i];
            alpha[(size_t)(j + 1) * Hh + col] = a;
            beta[(size_t)(j + 1) * Hh + col] = b;
        }
    }
}

// ---------------- PWL eval (merged graphs, vectorized) -----------------------
__global__ void k_pwl(const float* __restrict__ fe0, const float* __restrict__ fe1,
                      const int* __restrict__ esrc, const int* __restrict__ cnt,
                      const float* __restrict__ bt,
                      const float* __restrict__ alpha, const float* __restrict__ beta,
                      __half* __restrict__ Ehp) {
    int g = blockIdx.y;
    int p = blockIdx.x;
    if (p >= cnt[g]) return;
    const float* fe = g ? fe1 : fe0;
    float f = fe[esrc[g * MAXP + p]];
    int lo = 0, hi = 1024;
    while (lo < hi) {
        int m = (lo + hi) >> 1;
        if (__ldg(&bt[m]) <= f) lo = m + 1; else hi = m;
    }
    const float4* ra = (const float4*)(alpha + (size_t)lo * Hh);
    const float4* rb = (const float4*)(beta + (size_t)lo * Hh);
    __half* E1 = Ehp + (size_t)g * 2 * ((size_t)MAXP * Hh) + (size_t)p * Hh;
    int c4 = threadIdx.x * 2;
    float4 a0 = __ldg(&ra[c4]),     a1 = __ldg(&ra[c4 + 1]);
    float4 b0 = __ldg(&rb[c4]),     b1 = __ldg(&rb[c4 + 1]);
    __half2 h0 = __floats2half2_rn(fmaf(f, a0.x, b0.x), fmaf(f, a0.y, b0.y));
    __half2 h1 = __floats2half2_rn(fmaf(f, a0.z, b0.z), fmaf(f, a0.w, b0.w));
    __half2 h2 = __floats2half2_rn(fmaf(f, a1.x, b1.x), fmaf(f, a1.y, b1.y));
    __half2 h3 = __floats2half2_rn(fmaf(f, a1.z, b1.z), fmaf(f, a1.w, b1.w));
    uint4 o;
    o.x = *(uint32_t*)&h0; o.y = *(uint32_t*)&h1;
    o.z = *(uint32_t*)&h2; o.w = *(uint32_t*)&h3;
    *(uint4*)(E1 + threadIdx.x * 8) = o;
}

// ------------------- weight transpose fp16 (merged, z=weight) ---------------
__global__ void k_wh(const float* __restrict__ W0, const float* __restrict__ W1,
                     const float* __restrict__ W2, const float* __restrict__ W3,
                     const float* __restrict__ W4, const float* __restrict__ W5,
                     const float* __restrict__ W6, const float* __restrict__ W7,
                     const float* __restrict__ W8, __half* __restrict__ Tbase) {
    const float* Ws[9] = { W0, W1, W2, W3, W4, W5, W6, W7, W8 };
    const float* W = Ws[blockIdx.z];
    __half* Th = Tbase + (size_t)blockIdx.z * Hh * Hh;
    __shared__ float tile[32][33];
    int n0 = blockIdx.x << 5, k0 = blockIdx.y << 5;
    int tx = threadIdx.x, ty = threadIdx.y;
    for (int i = 0; i < 32; i += 8)
        tile[ty + i][tx] = W[(size_t)(k0 + ty + i) * Hh + n0 + tx];
    __syncthreads();
    for (int i = 0; i < 32; i += 8)
        Th[(size_t)(n0 + ty + i) * Hh + k0 + tx] = __float2half(tile[tx][ty + i]);
}

// ---------------- affinity transpose + hi/lo split (z=which) -----------------
__global__ void k_whl(const float* __restrict__ W0, const float* __restrict__ W1,
                      __half* __restrict__ ThB, __half* __restrict__ TlB) {
    const float* W = blockIdx.z ? W1 : W0;
    __half* Th = ThB + (size_t)blockIdx.z * Hh * Hh;
    __half* Tl = TlB + (size_t)blockIdx.z * Hh * Hh;
    __shared__ float tile[32][33];
    int n0 = blockIdx.x << 5, k0 = blockIdx.y << 5;
    int tx = threadIdx.x, ty = threadIdx.y;
    for (int i = 0; i < 32; i += 8)
        tile[ty + i][tx] = W[(size_t)(k0 + ty + i) * Hh + n0 + tx];
    __syncthreads();
    for (int i = 0; i < 32; i += 8) {
        float v = tile[tx][ty + i];
        __half h = __float2half(v);
        size_t o = (size_t)(n0 + ty + i) * Hh + k0 + tx;
        Th[o] = h;
        Tl[o] = __float2half(v - __half2float(h));
    }
}
__global__ void k_fh(const float* __restrict__ X0, const float* __restrict__ X1,
                     __half* __restrict__ H, int n) {
    int g = blockIdx.y;
    const float* X = g ? X1 : X0;
    int i = blockIdx.x * 256 + threadIdx.x;
    if (i < n) H[(size_t)g * n + i] = __float2half(X[i]);
}

// ---------------- layer-0 agg (merged graphs, 2 channels/thread) -------------
__global__ void k_agg0(const float* __restrict__ fe0, const float* __restrict__ fe1,
                       const int* __restrict__ esrc, const int* __restrict__ rowptr,
                       const int* __restrict__ colj, const float* __restrict__ aval,
                       const float* __restrict__ ew, const float* __restrict__ eb,
                       const float* __restrict__ ndx, const float* __restrict__ ndsx,
                       __half* __restrict__ oh) {
    __shared__ int   scol[Nn];
    __shared__ float sf[Nn];
    __shared__ float sa[Nn];
    int g = blockIdx.x >> 9;
    int r = blockIdx.x & 511;
    const float* fe = g ? fe1 : fe0;
    int b = r >> 6;
    int c = (blockIdx.y << 9) + threadIdx.x * 2;
    const int* rp = rowptr + g * (BN + 1);
    int s = rp[r], e = rp[r + 1];
    int n = e - s;
    if (threadIdx.x < n) {
        scol[threadIdx.x] = colj[g * MAXP + s + threadIdx.x];
        sf[threadIdx.x] = fe[esrc[g * MAXP + s + threadIdx.x]];
        sa[threadIdx.x] = aval[g * MAXP + s + threadIdx.x];
    }
    __syncthreads();
    const size_t MSZ = (size_t)BN * Hh;
    float2 w = *(const float2*)(ew + c);
    float2 bb = *(const float2*)(eb + c);
    float acc0 = 0.f, acc1 = 0.f;
    for (int q = 0; q < n; q++) {
        float2 nd = *(const float2*)(ndx + g * MSZ + (size_t)((b << 6) + scol[q]) * Hh + c);
        acc0 += sa[q] * (sf[q] * w.x + bb.x) * nd.x;
        acc1 += sa[q] * (sf[q] * w.y + bb.y) * nd.y;
    }
    float2 ns = *(const float2*)(ndsx + g * MSZ + (size_t)r * Hh + c);
    float v0 = fmaxf(acc0, 0.f) + fmaxf(ns.x, 0.f);
    float v1 = fmaxf(acc1, 0.f) + fmaxf(ns.y, 0.f);
    __half2 hv = __floats2half2_rn(v0, v1);
    *(__half2*)(oh + g * MSZ + (size_t)r * Hh + c) = hv;
}

// ---------------- agg with fp16 edges (merged, 2 ch/thread, +lo split) -------
__global__ void k_aggh(const __half* __restrict__ Ebase, const int* __restrict__ rowptr,
                       const int* __restrict__ colj, const float* __restrict__ aval,
                       const float* __restrict__ ndx, const float* __restrict__ ndsx,
                       float* __restrict__ embo, __half* __restrict__ oh,
                       __half* __restrict__ ol) {
    __shared__ int   scol[Nn];
    __shared__ float sa[Nn];
    int g = blockIdx.x >> 9;
    int r = blockIdx.x & 511;
    int b = r >> 6;
    int c = (blockIdx.y << 9) + threadIdx.x * 2;
    const int* rp = rowptr + g * (BN + 1);
    int s = rp[r], e = rp[r + 1];
    int n = e - s;
    if (threadIdx.x < n) {
        scol[threadIdx.x] = colj[g * MAXP + s + threadIdx.x];
        sa[threadIdx.x] = aval[g * MAXP + s + threadIdx.x];
    }
    __syncthreads();
    const size_t MSZ = (size_t)BN * Hh;
    const __half* E = Ebase + (size_t)g * 2 * ((size_t)MAXP * Hh);
    float acc0 = 0.f, acc1 = 0.f;
    for (int q = 0; q < n; q++) {
        __half2 ev = *(const __half2*)(E + (size_t)(s + q) * Hh + c);
        float2 nd = *(const float2*)(ndx + g * MSZ + (size_t)((b << 6) + scol[q]) * Hh + c);
        acc0 += sa[q] * __low2float(ev) * nd.x;
        acc1 += sa[q] * __high2float(ev) * nd.y;
    }
    float2 ns = *(const float2*)(ndsx + g * MSZ + (size_t)r * Hh + c);
    float v0 = fmaxf(acc0, 0.f) + fmaxf(ns.x, 0.f);
    float v1 = fmaxf(acc1, 0.f) + fmaxf(ns.y, 0.f);
    size_t o = g * MSZ + (size_t)r * Hh + c;
    if (embo) *(float2*)(embo + o) = make_float2(v0, v1);
    __half2 h2v = __floats2half2_rn(v0, v1);
    if (oh) *(__half2*)(oh + o) = h2v;
    if (ol) {
        float l0 = v0 - __half2float(__low2half(h2v));
        float l1 = v1 - __half2float(__high2half(h2v));
        *(__half2*)(ol + o) = __floats2half2_rn(l0, l1);
    }
}

// ------------- batched NT GEMM K-split: Sp[z][b] = T[b]@E[b]^T (K chunk) -----
__global__ void __launch_bounds__(256)
k_bmm_nt(const float* __restrict__ T, const float* __restrict__ E, float* __restrict__ Sp) {
    int b = blockIdx.x, zk = blockIdx.y;
    const float* Tb = T + (size_t)b * Nn * Hh;
    const float* Eb = E + (size_t)b * Nn * Hh;
    __shared__ float Ts[16][68];
    __shared__ float Es[16][68];
    int t = threadIdx.x, tx = t & 15, ty = t >> 4;
    int lr = t >> 2, lk = (t & 3) << 2;
    float acc[4][4];
#pragma unroll
    for (int i = 0; i < 4; i++)
#pragma unroll
        for (int j = 0; j < 4; j++) acc[i][j] = 0.f;
    int kbeg = zk << 8;
    for (int k0 = kbeg; k0 < kbeg + 256; k0 += 16) {
        float4 a = *(const float4*)(Tb + (size_t)lr * Hh + k0 + lk);
        float4 e = *(const float4*)(Eb + (size_t)lr * Hh + k0 + lk);
        __syncthreads();
        Ts[lk + 0][lr] = a.x; Ts[lk + 1][lr] = a.y; Ts[lk + 2][lr] = a.z; Ts[lk + 3][lr] = a.w;
        Es[lk + 0][lr] = e.x; Es[lk + 1][lr] = e.y; Es[lk + 2][lr] = e.z; Es[lk + 3][lr] = e.w;
        __syncthreads();
#pragma unroll
        for (int k = 0; k < 16; k++) {
            float4 av = *(float4*)&Ts[k][ty << 2];
            float4 bv = *(float4*)&Es[k][tx << 2];
            acc[0][0] += av.x * bv.x; acc[0][1] += av.x * bv.y; acc[0][2] += av.x * bv.z; acc[0][3] += av.x * bv.w;
            acc[1][0] += av.y * bv.x; acc[1][1] += av.y * bv.y; acc[1][2] += av.y * bv.z; acc[1][3] += av.y * bv.w;
            acc[2][0] += av.z * bv.x; acc[2][1] += av.z * bv.y; acc[2][2] += av.z * bv.z; acc[2][3] += av.z * bv.w;
            acc[3][0] += av.w * bv.x; acc[3][1] += av.w * bv.y; acc[3][2] += av.w * bv.z; acc[3][3] += av.w * bv.w;
        }
    }
    float* out = Sp + ((size_t)zk * Bb + b) * (Nn * Nn);
#pragma unroll
    for (int ii = 0; ii < 4; ii++)
#pragma unroll
        for (int jj = 0; jj < 4; jj++)
            out[((ty << 2) + ii) * Nn + (tx << 2) + jj] = acc[ii][jj];
}

// ---------------- U (merged): g=0: s@emb2 ; g=1: s^T@emb1 --------------------
__global__ void k_su(const float* __restrict__ S, const float* __restrict__ Emb1,
                     const float* __restrict__ Emb2, __half* __restrict__ Uh) {
    int idx = blockIdx.x;
    int g = idx >> 9;
    int blk = idx & 511;
    int b = blk >> 6, i = blk & 63;
    const float* Emb = g ? Emb1 : Emb2;
    __shared__ float srow[Nn];
    int t = threadIdx.x;
    if (t < Nn)
        srow[t] = g ? S[b * (Nn * Nn) + t * Nn + i]
                    : S[b * (Nn * Nn) + i * Nn + t];
    __syncthreads();
    const size_t MSZ = (size_t)BN * Hh;
    for (int c = t; c < Hh; c += 256) {
        float acc = 0.f;
#pragma unroll 8
        for (int j = 0; j < Nn; j++)
            acc += srow[j] * Emb[(size_t)((b << 6) + j) * Hh + c];
        Uh[g * MSZ + (size_t)blk * Hh + c] = __float2half(acc);
    }
}

// ---------------- sinkhorn (reads sum of 4 K-split partials) -----------------
__global__ void k_sinkhorn(const float* __restrict__ Sp, float* __restrict__ out,
                           const int* __restrict__ n1, const int* __restrict__ n2,
                           const int* __restrict__ itp) {
    __shared__ float ls[64][65];
    int b = blockIdx.x, t = threadIdx.x;
    int a1 = n1[b], a2 = n2[b];
    int tb = (a1 > a2);
    int nr = tb ? a2 : a1;
    int nc = tb ? a1 : a2;
    for (int e = t; e < 4096; e += 256) {
        int r = e >> 6, c = e & 63;
        int idx = tb ? (c * 64 + r) : (r * 64 + c);
        float v = 0.f;
#pragma unroll
        for (int zz = 0; zz < 4; zz++)
            v += Sp[((size_t)zz * Bb + b) * 4096 + idx];
        ls[r][c] = (r < nr && c < nc) ? v / 0.05f : NEGV;
    }
    __syncthreads();
    int iters = *itp;
    int w = t >> 5, lane = t & 31;
    for (int it = 0; it < iters; it++) {
        if ((it & 1) == 0) {
            for (int r = w; r < 64; r += 8) {
                float x0 = ls[r][lane], x1 = ls[r][lane + 32];
                float m = fmaxf(x0, x1);
                for (int o = 16; o; o >>= 1) m = fmaxf(m, __shfl_xor_sync(0xffffffffu, m, o));
                float sm = expf(x0 - m) + expf(x1 - m);
                for (int o = 16; o; o >>= 1) sm += __shfl_xor_sync(0xffffffffu, sm, o);
                float lse = m + logf(sm);
                bool rm = (r < nr);
                ls[r][lane]      = (rm && lane < nc)        ? x0 - lse : NEGV;
                ls[r][lane + 32] = (rm && (lane + 32) < nc) ? x1 - lse : NEGV;
            }
        } else {
            for (int c = w; c < 64; c += 8) {
                float x0 = ls[lane][c], x1 = ls[lane + 32][c];
                float m = fmaxf(x0, x1);
                for (int o = 16; o; o >>= 1) m = fmaxf(m, __shfl_xor_sync(0xffffffffu, m, o));
                float sm = expf(x0 - m) + expf(x1 - m);
                for (int o = 16; o; o >>= 1) sm += __shfl_xor_sync(0xffffffffu, sm, o);
                float lse = m + logf(sm);
                bool cm = (c < nc);
                ls[lane][c]      = (cm && lane < nr)        ? x0 - lse : NEGV;
                ls[lane + 32][c] = (cm && (lane + 32) < nr) ? x1 - lse : NEGV;
            }
        }
        __syncthreads();
    }
    for (int e = t; e < 4096; e += 256) {
        int r = e >> 6, c = e & 63;
        float v = (r < nr && c < nc) ? expf(ls[r][c]) : 0.f;
        if (tb) out[b * 4096 + c * 64 + r] = v;
        else    out[b * 4096 + r * 64 + c] = v;
    }
}

// ------------------------------- launch --------------------------------------
extern "C" void kernel_launch(void* const* d_in, const int* in_sizes, int n_in,
                              void* d_out, int out_size) {
    (void)in_sizes; (void)n_in; (void)out_size;
    const float* fn[2]   = { (const float*)d_in[0], (const float*)d_in[1] };
    const float* Aadj[2] = { (const float*)d_in[2], (const float*)d_in[3] };
    const float* fe[2]   = { (const float*)d_in[4], (const float*)d_in[5] };
    const float* lw[3][6];
    for (int l = 0; l < 3; l++)
        for (int k = 0; k < 6; k++)
            lw[l][k] = (const float*)d_in[6 + l * 6 + k];
    const float* aff1 = (const float*)d_in[24];
    const float* aff2 = (const float*)d_in[25];
    const float* cw   = (const float*)d_in[26];
    const float* cb   = (const float*)d_in[27];
    const int*   n1   = (const int*)d_in[28];
    const int*   n2   = (const int*)d_in[29];
    const int*   itp  = (const int*)d_in[30];
    float* out = (float*)d_out;

    void* p;
    cudaGetSymbolAddress(&p, g_Ehp);    __half* Ehp   = (__half*)p;
    cudaGetSymbolAddress(&p, g_emb32);  float*  emb32 = (float*)p;
    cudaGetSymbolAddress(&p, g_embh);   __half* ebh   = (__half*)p;
    cudaGetSymbolAddress(&p, g_embl);   __half* ebl   = (__half*)p;
    cudaGetSymbolAddress(&p, g_ndx);    float*  ndx   = (float*)p;
    cudaGetSymbolAddress(&p, g_ndsx);   float*  ndsx  = (float*)p;
    cudaGetSymbolAddress(&p, g_t);      float*  tbuf  = (float*)p;
    cudaGetSymbolAddress(&p, g_uh);     __half* uh    = (__half*)p;
    cudaGetSymbolAddress(&p, g_fnh);    __half* fnh   = (__half*)p;
    cudaGetSymbolAddress(&p, g_wth);    __half* wth   = (__half*)p;
    cudaGetSymbolAddress(&p, g_afh);    __half* afh   = (__half*)p;
    cudaGetSymbolAddress(&p, g_afl);    __half* afl   = (__half*)p;
    cudaGetSymbolAddress(&p, g_alpha);  float*  alpha = (float*)p;
    cudaGetSymbolAddress(&p, g_beta);   float*  beta  = (float*)p;
    cudaGetSymbolAddress(&p, g_bt);     float*  bt    = (float*)p;
    cudaGetSymbolAddress(&p, g_bc);     int*    bc    = (int*)p;
    cudaGetSymbolAddress(&p, g_b0a);    float*  b0a   = (float*)p;
    cudaGetSymbolAddress(&p, g_b0b);    float*  b0b   = (float*)p;
    cudaGetSymbolAddress(&p, g_da);     float*  da    = (float*)p;
    cudaGetSymbolAddress(&p, g_db);     float*  db    = (float*)p;
    cudaGetSymbolAddress(&p, g_offa);   float*  offa  = (float*)p;
    cudaGetSymbolAddress(&p, g_offb);   float*  offb  = (float*)p;
    cudaGetSymbolAddress(&p, g_spart);  float*  spart = (float*)p;
    cudaGetSymbolAddress(&p, g_ssk);    float*  ssk   = (float*)p;
    cudaGetSymbolAddress(&p, g_rowcnt); int* rowcnt   = (int*)p;
    cudaGetSymbolAddress(&p, g_rowptr); int* rowptr   = (int*)p;
    cudaGetSymbolAddress(&p, g_colj);   int* colj     = (int*)p;
    cudaGetSymbolAddress(&p, g_esrc);   int* esrc     = (int*)p;
    cudaGetSymbolAddress(&p, g_aval);   float* aval   = (float*)p;
    cudaGetSymbolAddress(&p, g_cnt);    int* cnt      = (int*)p;

    const size_t ESZ = (size_t)MAXP * Hh;
    const size_t MSZ = (size_t)BN * Hh;
    const size_t WSZ = (size_t)Hh * Hh;
#define E1P(g)     (Ehp + ((size_t)(g) * 2 + 0) * ESZ)
#define M32(g)     (emb32 + (size_t)(g) * MSZ)
#define EBH(pp, g) (ebh + ((size_t)(pp) * 2 + (g)) * MSZ)
#define WH(i)      (wth + (size_t)(i) * WSZ)

    cudaStream_t s0 = 0;
    cudaStream_t s2 = g_si.s2;
    cudaStream_t s3 = g_si.s3;

    // ---- fork ----
    cudaEventRecord(g_si.evRoot, s0);
    cudaStreamWaitEvent(s2, g_si.evRoot, 0);
    cudaStreamWaitEvent(s3, g_si.evRoot, 0);

    // ---- s3: compaction chain (independent of weights/features) ----
    k_count<<<dim3(8, 2), 64, 0, s3>>>(Aadj[0], Aadj[1], rowcnt);
    k_scan<<<2, BN, 0, s3>>>(rowcnt, rowptr, cnt);
    k_fill<<<dim3(8, 2), 64, 0, s3>>>(Aadj[0], Aadj[1], rowptr, colj, esrc, aval);
    cudaEventRecord(g_si.evA, s3);              // compaction ready

    // ---- s2: affinity splits + PWL table build ----
    k_whl<<<dim3(32, 32, 2), dim3(32, 8), 0, s2>>>(aff1, aff2, afh, afl);
    cudaEventRecord(g_si.evE, s2);              // aff splits ready
    k_sort<<<1, 1024, 0, s2>>>(lw[0][4], lw[0][5], bt, bc);
    k_bd<<<dim3(8, 16, 2), 128, 0, s2>>>(lw[0][4], lw[0][5], lw[1][4], lw[1][5], bc,
                                         b0a, b0b, da, db);
    k_offs<<<8, 128, 0, s2>>>(b0a, b0b, da, db, offa, offb, alpha, beta);
    k_fillscan<<<dim3(8, 16), 128, 0, s2>>>(lw[0][4], lw[0][5], lw[1][4], bc,
                                            offa, offb, alpha, beta);

    // ---- s0: weights + features (no compaction dependency) ----
    k_wh<<<dim3(32, 32, 9), dim3(32, 8), 0, s0>>>(lw[0][0], lw[0][2], lw[1][0], lw[1][2],
                                                  lw[2][0], lw[2][2], lw[2][4], cw,
                                                  cw + WSZ, wth);
    cudaEventRecord(g_si.evW, s0);              // weights ready (for E2 GEMM on s2)
    k_fh<<<dim3((int)(MSZ / 256), 2), 256, 0, s0>>>(fn[0], fn[1], fnh, (int)MSZ);

    // ---- s2: E1 eval + E2 GEMM (fp16-acc, proven safe) ----
    cudaStreamWaitEvent(s2, g_si.evA, 0);
    k_pwl<<<dim3(MAXP, 2), 128, 0, s2>>>(fe[0], fe[1], esrc, cnt, bt, alpha, beta, Ehp);
    cudaEventRecord(g_si.evB, s2);              // E1 ready
    cudaStreamWaitEvent(s2, g_si.evW, 0);
    k_h16<<<dim3(256, 8, 2), 256, 0, s2>>>(E1P(0), E1P(1), WH(6), lw[2][5],
                                           Ehp + ESZ, Ehp + 3 * ESZ, cnt);
    cudaEventRecord(g_si.evD, s2);              // E2 ready

    // ---- s0: node layers 0-1 (fp32 acc — measured faster) ----
    k_hgemm<<<dim3(8, 8, 2), 256, 0, s0>>>(fnh, nullptr, nullptr, nullptr,
                                           WH(0), WH(1), nullptr, nullptr,
                                           lw[0][1], lw[0][3], ndx, ndsx,
                                           nullptr, nullptr, 0, 0, 0, 2 * BN, nullptr);
    cudaStreamWaitEvent(s0, g_si.evA, 0);       // agg0 needs compaction
    k_agg0<<<dim3(1024, 2), 256, 0, s0>>>(fe[0], fe[1], esrc, rowptr, colj, aval,
                                          lw[0][4], lw[0][5], ndx, ndsx, EBH(0, 0));
    k_hgemm<<<dim3(8, 8, 2), 256, 0, s0>>>(EBH(0, 0), nullptr, nullptr, nullptr,
                                           WH(2), WH(3), nullptr, nullptr,
                                           lw[1][1], lw[1][3], ndx, ndsx,
                                           nullptr, nullptr, 0, 0, 0, 2 * BN, nullptr);
    cudaStreamWaitEvent(s0, g_si.evB, 0);
    k_aggh<<<dim3(1024, 2), 256, 0, s0>>>(E1P(0), rowptr, colj, aval, ndx, ndsx,
                                          M32(0), EBH(1, 0), ebl);
    // ---- cross-attention mid-section (overlaps E2 GEMM on s2) ----
    cudaStreamWaitEvent(s0, g_si.evE, 0);       // need aff splits
    k_hgemm<<<dim3(4, 8, 1), 256, 0, s0>>>(EBH(1, 0), nullptr, EBH(1, 0), ebl,
                                           afh, nullptr, afl, afh,
                                           nullptr, nullptr, tbuf, nullptr,
                                           nullptr, nullptr, 0, 0, 0, BN, nullptr);
    k_bmm_nt<<<dim3(8, 4), 256, 0, s0>>>(tbuf, M32(1), spart);
    k_sinkhorn<<<8, 256, 0, s0>>>(spart, ssk, n1, n2, itp);
    k_su<<<1024, 256, 0, s0>>>(ssk, M32(0), M32(1), uh);
    k_hgemm<<<dim3(8, 8, 1), 256, 0, s0>>>(EBH(1, 0), nullptr, uh, nullptr,
                                           WH(7), nullptr, WH(8), nullptr,
                                           cb, nullptr, nullptr, nullptr,
                                           EBH(0, 0), nullptr, 0, 0, 0, 2 * BN, nullptr);
    k_hgemm<<<dim3(8, 8, 2), 256, 0, s0>>>(EBH(0, 0), nullptr, nullptr, nullptr,
                                           WH(4), WH(5), nullptr, nullptr,
                                           lw[2][1], lw[2][3], ndx, ndsx,
                                           nullptr, nullptr, 0, 0, 0, 2 * BN, nullptr);
    // ---- join: layer-2 agg needs E2; M32 write REQUIRED (final bmm reads it) -
    cudaStreamWaitEvent(s0, g_si.evD, 0);
    k_aggh<<<dim3(1024, 2), 256, 0, s0>>>(Ehp + ESZ, rowptr, colj, aval, ndx, ndsx,
                                          M32(0), EBH(1, 0), ebl);
    // ---- final affinity + sinkhorn ----
    k_hgemm<<<dim3(4, 8, 1), 256, 0, s0>>>(EBH(1, 0), nullptr, EBH(1, 0), ebl,
                                           afh + WSZ, nullptr, afl + WSZ, afh + WSZ,
                                           nullptr, nullptr, tbuf, nullptr,
                                           nullptr, nullptr, 0, 0, 0, BN, nullptr);
    k_bmm_nt<<<dim3(8, 4), 256, 0, s0>>>(tbuf, M32(1), spart);
    k_sinkhorn<<<8, 256, 0, s0>>>(spart, out, n1, n2, itp);
#undef E1P
#undef M32
#undef EBH
#undef WH
}